// round 12
// baseline (speedup 1.0000x reference)
#include <cuda_runtime.h>
#include <cstddef>

#define T_STEPS 300
#define TS_U8   304          // padded stride for u8 spike tensors (16B aligned)
#define THETA 10.0f

// ---------------- scratch ----------------
__device__ float g_bufA[39321600];          // byte-region reused: x_u8 / s4 / u5 / u6
__device__ unsigned char g_bufS[9961472];   // s2 / s5
__device__ float g_bufW[32000];             // packed weights

#define W1_OFF 0
#define W2_OFF 1280
#define W3_OFF 7424

// REF_KERNEL[1..10]: -20*t*exp(1-t), t=1..10 (fp32-rounded from double)
__constant__ float c_refk[10] = {
    -20.0f,
    -14.715177646857693f,
    -8.1201169941967624f,
    -3.9829654694291156f,
    -1.8315638888734179f,
    -0.80855363989025606f,
    -0.34702530473329019f,
    -0.14590111448872260f,
    -0.060383273022452132f,
    -0.024681960817335913f
};

__device__ __forceinline__ float spike_step(float u, float (&buf)[10]) {
    float um = u + buf[0];
    float e = (um >= THETA) ? 1.0f : 0.0f;
#pragma unroll
    for (int j = 0; j < 9; j++) buf[j] = buf[j + 1] + e * c_refk[j];
    buf[9] = e * c_refk[9];
    return e;   // TS = 1 -> amplitude 1
}

// packed 2x fp32 fma (Blackwell FFMA2). Bit-identical to two fmaf's.
__device__ __forceinline__ void ffma2(float2& c, float2 a, float2 b) {
    unsigned long long au = *reinterpret_cast<unsigned long long*>(&a);
    unsigned long long bu = *reinterpret_cast<unsigned long long*>(&b);
    unsigned long long cu = *reinterpret_cast<unsigned long long*>(&c);
    asm("fma.rn.f32x2 %0, %1, %2, %0;" : "+l"(cu) : "l"(au), "l"(bu));
    *reinterpret_cast<unsigned long long*>(&c) = cu;
}

__device__ __forceinline__ void ffma4(float4& c, const float4& a, float w) {
    float2 wv = make_float2(w, w);
    float2 clo = make_float2(c.x, c.y), chi = make_float2(c.z, c.w);
    ffma2(clo, make_float2(a.x, a.y), wv);
    ffma2(chi, make_float2(a.z, a.w), wv);
    c.x = clo.x; c.y = clo.y; c.z = chi.x; c.w = chi.y;
}

__device__ __forceinline__ float f4_get(const float4& v, int i) {
    return i == 0 ? v.x : i == 1 ? v.y : i == 2 ? v.z : v.w;
}

__device__ __forceinline__ float4 load_quad(const float* p) {
    return *(const float4*)p;
}
__device__ __forceinline__ float4 load_quad(const unsigned char* p) {
    uchar4 c = *(const uchar4*)p;
    return make_float4((float)c.x, (float)c.y, (float)c.z, (float)c.w);
}

// ---------------- weight packing: [co][ci][ky][WROW] 16B-aligned rows ---------
__global__ void pack_weights_kernel(const float* __restrict__ w1,
                                    const float* __restrict__ w2,
                                    const float* __restrict__ w3,
                                    float* __restrict__ wp)
{
    int i = blockIdx.x * blockDim.x + threadIdx.x;
    if (i < 1280) {                       // w1: [16][2][5][8]
        int kx = i % 8; int r = i / 8;
        int ky = r % 5; r /= 5;
        int ci = r % 2; int co = r / 2;
        wp[W1_OFF + i] = (kx < 5) ? w1[((co * 2 + ci) * 5 + ky) * 5 + kx] : 0.0f;
    } else if (i < 1280 + 6144) {         // w2: [32][16][3][4]
        int k = i - 1280;
        int kx = k % 4; int r = k / 4;
        int ky = r % 3; r /= 3;
        int ci = r % 16; int co = r / 16;
        wp[W2_OFF + k] = (kx < 3) ? w2[((co * 16 + ci) * 3 + ky) * 3 + kx] : 0.0f;
    } else if (i < 1280 + 6144 + 24576) { // w3: [64][32][3][4]
        int k = i - 1280 - 6144;
        int kx = k % 4; int r = k / 4;
        int ky = r % 3; r /= 3;
        int ci = r % 32; int co = r / 32;
        wp[W3_OFF + k] = (kx < 3) ? w3[((co * 32 + ci) * 3 + ky) * 3 + kx] : 0.0f;
    }
}

// ---------------- input fp32 {0,1} -> u8 (exact) ----------------
__global__ void x_to_u8_kernel(const float* __restrict__ x, unsigned char* __restrict__ y)
{
    int i = blockIdx.x * blockDim.x + threadIdx.x;
    if (i < 1387200) {
        float4 v = ((const float4*)x)[i];
        ((uchar4*)y)[i] = make_uchar4((unsigned char)v.x, (unsigned char)v.y,
                                      (unsigned char)v.z, (unsigned char)v.w);
    }
}

// ================ FUSED layer1: conv(2->16,5x5,p1) + spike + pool + spike =====
// grid 128 = b(8) x Y(16 pooled rows); threads 256: tid = co + 16*px.
// Thread owns 4 parents (rows 2Y,2Y+1 x cols 2px,2px+1) + pooled neuron for
// all 300 timesteps; u1 never hits DRAM. Tile: [ci2][row6][col36][tq25] float4.
#define C1_TPQ 25
__global__ void __launch_bounds__(256)
conv1sp_kernel(const unsigned char* __restrict__ x, const float* __restrict__ w,
               unsigned char* __restrict__ s2)
{
    extern __shared__ float4 tile[];   // 2*6*36*25 = 10800
    int Y = blockIdx.x & 15;
    int b = blockIdx.x >> 4;
    int tid = threadIdx.x;
    int co = tid & 15, px = tid >> 4;

    float bufP[4][10], bufQ[10];
#pragma unroll
    for (int j = 0; j < 10; j++) {
        bufP[0][j] = 0.f; bufP[1][j] = 0.f; bufP[2][j] = 0.f; bufP[3][j] = 0.f;
        bufQ[j] = 0.f;
    }
    unsigned int wbuf[4];
    unsigned char* sp = s2 + (size_t)(((b * 16 + co) * 16 + Y) * 16 + px) * TS_U8;

    for (int ch = 0; ch < 3; ch++) {
        int t0 = ch * 100;
        for (int f = tid; f < 10800; f += 256) {
            int tq = f % 25; int r = f / 25;
            int col = r % 36; r /= 36;
            int row = r % 6;  int ci = r / 6;
            int xi = col - 1, yi = 2 * Y - 1 + row, t = t0 + 4 * tq;
            float4 v = make_float4(0.f, 0.f, 0.f, 0.f);
            if (xi >= 0 && xi < 34 && yi >= 0 && yi < 34)
                v = load_quad(&x[(size_t)(((b * 2 + ci) * 34 + yi) * 34 + xi) * T_STEPS + t]);
            tile[f] = v;
        }
        __syncthreads();

        for (int tq = 0; tq < C1_TPQ; tq++) {
            float4 acc[2][2];
            acc[0][0] = acc[0][1] = acc[1][0] = acc[1][1] = make_float4(0.f, 0.f, 0.f, 0.f);
#pragma unroll
            for (int ci = 0; ci < 2; ci++) {
                const float4* tb = &tile[(size_t)(ci * 6 * 36 + 2 * px) * 25 + tq];
                float4 win[2][6];
#pragma unroll
                for (int j = 0; j < 6; j++) win[0][j] = tb[j * 25];
#pragma unroll
                for (int j = 0; j < 6; j++) win[1][j] = tb[(36 + j) * 25];
#pragma unroll
                for (int ky = 0; ky < 5; ky++) {
                    const float4* wr = (const float4*)&w[((co * 2 + ci) * 5 + ky) * 8];
                    float4 w0 = wr[0], w1 = wr[1];
#pragma unroll
                    for (int kx = 0; kx < 5; kx++) {
                        float wv = (kx < 4) ? f4_get(w0, kx) : f4_get(w1, 0);
#pragma unroll
                        for (int dy = 0; dy < 2; dy++)
#pragma unroll
                            for (int dx = 0; dx < 2; dx++)
                                ffma4(acc[dy][dx], win[(ky + dy) & 1][kx + dx], wv);
                    }
                    if (ky < 4) {
#pragma unroll
                        for (int j = 0; j < 6; j++)
                            win[ky & 1][j] = tb[((ky + 2) * 36 + j) * 25];
                    }
                }
            }
            unsigned int e4 = 0;
#pragma unroll
            for (int l = 0; l < 4; l++) {
                float p00 = spike_step(f4_get(acc[0][0], l), bufP[0]);
                float p01 = spike_step(f4_get(acc[0][1], l), bufP[1]);
                float p10 = spike_step(f4_get(acc[1][0], l), bufP[2]);
                float p11 = spike_step(f4_get(acc[1][1], l), bufP[3]);
                float s = p00 + p01 + p10 + p11;     // ints -> exact
                unsigned int e = (unsigned int)spike_step(11.0f * s, bufQ);
                e4 |= e << (8 * l);
            }
            int gq = ch * 25 + tq;
            wbuf[gq & 3] = e4;
            if ((gq & 3) == 3)
                ((uint4*)sp)[gq >> 2] = make_uint4(wbuf[0], wbuf[1], wbuf[2], wbuf[3]);
        }
        __syncthreads();
    }
    ((unsigned int*)sp)[72] = wbuf[0];
    ((unsigned int*)sp)[73] = wbuf[1];
    ((unsigned int*)sp)[74] = wbuf[2];
}

// ================ FUSED layer2: conv(16->32,3x3,p1) + spike + pool + spike ====
// grid 128 = b(8) x Y(8) x coHalf(2); threads 256: tid = dy + 2*co + 32*px.
// Thread owns 2 parents (row 2Y+dy, cols 2px,2px+1); dy-pair pooled via shfl.
// Tile: [ci16][row4][col18][tq5] float4 = 92160 B, 15 chunks of 20 steps.
#define C2_TPQ 5
__global__ void __launch_bounds__(256)
conv2sp_kernel(const unsigned char* __restrict__ s2in, const float* __restrict__ w,
               unsigned char* __restrict__ s4)
{
    extern __shared__ float4 tile2[];  // 16*4*18*5 = 5760
    int half = blockIdx.x & 1;
    int Y    = (blockIdx.x >> 1) & 7;
    int b    = blockIdx.x >> 4;
    int tid = threadIdx.x;
    int dy = tid & 1, co = (tid >> 1) & 15, px = tid >> 5;
    int cog = half * 16 + co;

    float bufP[2][10], bufQ[10];
#pragma unroll
    for (int j = 0; j < 10; j++) { bufP[0][j] = 0.f; bufP[1][j] = 0.f; bufQ[j] = 0.f; }
    unsigned int wbuf[4];
    unsigned char* sp = s4 + (size_t)(((b * 32 + cog) * 8 + Y) * 8 + px) * TS_U8;

    for (int ch = 0; ch < 15; ch++) {
        int t0 = ch * 20;
        for (int f = tid; f < 5760; f += 256) {
            int tq = f % 5; int r = f / 5;
            int col = r % 18; r /= 18;
            int row = r % 4;  int ci = r / 4;
            int xi = col - 1, yi = 2 * Y - 1 + row, t = t0 + 4 * tq;
            float4 v = make_float4(0.f, 0.f, 0.f, 0.f);
            if (xi >= 0 && xi < 16 && yi >= 0 && yi < 16)
                v = load_quad(&s2in[(size_t)(((b * 16 + ci) * 16 + yi) * 16 + xi) * TS_U8 + t]);
            tile2[f] = v;
        }
        __syncthreads();

        for (int tq = 0; tq < C2_TPQ; tq++) {
            float4 acc[2];
            acc[0] = acc[1] = make_float4(0.f, 0.f, 0.f, 0.f);
            for (int ci = 0; ci < 16; ci++) {
                const float4* tb = &tile2[(size_t)((ci * 4 + dy) * 18 + 2 * px) * 5 + tq];
                float4 win[3][4];
#pragma unroll
                for (int r3 = 0; r3 < 3; r3++)
#pragma unroll
                    for (int j = 0; j < 4; j++) win[r3][j] = tb[r3 * 90 + j * 5];
                const float4* wr = (const float4*)&w[(size_t)(cog * 16 + ci) * 12];
#pragma unroll
                for (int ky = 0; ky < 3; ky++) {
                    float4 wk = wr[ky];
#pragma unroll
                    for (int kx = 0; kx < 3; kx++) {
                        float wv = f4_get(wk, kx);
                        ffma4(acc[0], win[ky][kx],     wv);
                        ffma4(acc[1], win[ky][kx + 1], wv);
                    }
                }
            }
            unsigned int e4 = 0;
#pragma unroll
            for (int l = 0; l < 4; l++) {
                float p0 = spike_step(f4_get(acc[0], l), bufP[0]);
                float p1 = spike_step(f4_get(acc[1], l), bufP[1]);
                float own = p0 + p1;
                float oth = __shfl_xor_sync(0xffffffffu, own, 1);
                float s = own + oth;                 // ints -> exact
                unsigned int e = (unsigned int)spike_step(11.0f * s, bufQ);
                e4 |= e << (8 * l);
            }
            int gq = ch * 5 + tq;
            wbuf[gq & 3] = e4;
            if ((gq & 3) == 3 && dy == 0)
                ((uint4*)sp)[gq >> 2] = make_uint4(wbuf[0], wbuf[1], wbuf[2], wbuf[3]);
        }
        __syncthreads();
    }
    if (dy == 0) {
        ((unsigned int*)sp)[72] = wbuf[0];
        ((unsigned int*)sp)[73] = wbuf[1];
        ((unsigned int*)sp)[74] = wbuf[2];
    }
}

// ---------------- conv3 (unfused): u8 in, float out, packed weights ------------
template <typename IT, int IN_TS,
          int Ci, int Hi, int Wi, int Co, int Ho, int Wo, int K, int PAD, int TPQ,
          int WROW>
__global__ void __launch_bounds__(TPQ * 32, 2)
conv_kernel(const IT* __restrict__ in, const float* __restrict__ w,
            float* __restrict__ out)
{
    constexpr int WT  = Wo + K - 1;
    constexpr int XR  = 4;
    constexpr int COB = 4;
    constexpr int XG  = Wo / XR;
    constexpr int CG  = Co / COB;
    static_assert(XG * CG == 32, "one item per ty");
    constexpr int TCH = 4 * TPQ;
    constexpr int NTC = (T_STEPS + TCH - 1) / TCH;
    constexpr int NTH = TPQ * 32;

    extern __shared__ char smraw[];
    float4* sm4 = (float4*)smraw;

    int bid = blockIdx.x;
    int tc  = bid % NTC;
    int yo  = (bid / NTC) % Ho;
    int b   = bid / (NTC * Ho);
    int t0  = tc * TCH;

    int tid = threadIdx.y * TPQ + threadIdx.x;

    constexpr int TILE4 = Ci * K * WT * TPQ;
    for (int flat = tid; flat < TILE4; flat += NTH) {
        int tt = flat % TPQ;
        int r  = flat / TPQ;
        int xw = r % WT; r /= WT;
        int ky = r % K;
        int ci = r / K;
        int xi = xw - PAD;
        int yi = yo - PAD + ky;
        int t  = t0 + 4 * tt;
        float4 v = make_float4(0.0f, 0.0f, 0.0f, 0.0f);
        if (xi >= 0 && xi < Wi && yi >= 0 && yi < Hi && t < T_STEPS)
            v = load_quad(&in[((((size_t)b * Ci + ci) * Hi + yi) * Wi + xi) * IN_TS + t]);
        sm4[flat] = v;
    }
    __syncthreads();

    int tx = threadIdx.x;
    int t  = t0 + 4 * tx;
    int item = threadIdx.y;
    int co0 = (item / XG) * COB;
    int xo0 = (item % XG) * XR;

    float4 acc[COB][XR];
#pragma unroll
    for (int j = 0; j < COB; j++)
#pragma unroll
        for (int r = 0; r < XR; r++) acc[j][r] = make_float4(0.0f, 0.0f, 0.0f, 0.0f);

    for (int ci = 0; ci < Ci; ci++) {
#pragma unroll
        for (int ky = 0; ky < K; ky++) {
            float4 v[K + XR - 1];
            const float4* sp = &sm4[((ci * K + ky) * WT + xo0) * TPQ + tx];
#pragma unroll
            for (int j = 0; j < K + XR - 1; j++) v[j] = sp[j * TPQ];
            float4 wq[COB][WROW / 4];
#pragma unroll
            for (int j = 0; j < COB; j++)
#pragma unroll
                for (int p = 0; p < WROW / 4; p++)
                    wq[j][p] = *(const float4*)&w[(((size_t)(co0 + j) * Ci + ci) * K + ky) * WROW + 4 * p];
#pragma unroll
            for (int kx = 0; kx < K; kx++)
#pragma unroll
                for (int j = 0; j < COB; j++)
#pragma unroll
                    for (int r = 0; r < XR; r++)
                        ffma4(acc[j][r], v[kx + r], f4_get(wq[j][kx >> 2], kx & 3));
        }
    }

    if (t < T_STEPS) {
#pragma unroll
        for (int j = 0; j < COB; j++)
#pragma unroll
            for (int r = 0; r < XR; r++)
                *(float4*)&out[((((size_t)b * Co + co0 + j) * Ho + yo) * Wo + xo0 + r) * T_STEPS + t]
                    = acc[j][r];
    }
}

// ---------------- spike with u8 output (layer 5), pipelined ----------------
__global__ void __launch_bounds__(256)
spike_u8_kernel(const float* __restrict__ u, unsigned char* __restrict__ s, int nNeurons)
{
    int n = blockIdx.x * blockDim.x + threadIdx.x;
    if (n >= nNeurons) return;
    const float4* up = (const float4*)(u + (size_t)n * T_STEPS);
    unsigned char* sp = s + (size_t)n * TS_U8;
    float buf[10];
#pragma unroll
    for (int j = 0; j < 10; j++) buf[j] = 0.0f;

    for (int g = 0; g < 18; g++) {
        float4 v[4];
#pragma unroll
        for (int i = 0; i < 4; i++) v[i] = up[g * 4 + i];
        unsigned int wd[4];
#pragma unroll
        for (int i = 0; i < 4; i++) {
            unsigned int e0 = (unsigned int)spike_step(v[i].x, buf);
            unsigned int e1 = (unsigned int)spike_step(v[i].y, buf);
            unsigned int e2 = (unsigned int)spike_step(v[i].z, buf);
            unsigned int e3 = (unsigned int)spike_step(v[i].w, buf);
            wd[i] = e0 | (e1 << 8) | (e2 << 16) | (e3 << 24);
        }
        ((uint4*)sp)[g] = make_uint4(wd[0], wd[1], wd[2], wd[3]);
    }
    {
        float4 v[3];
#pragma unroll
        for (int i = 0; i < 3; i++) v[i] = up[72 + i];
#pragma unroll
        for (int i = 0; i < 3; i++) {
            unsigned int e0 = (unsigned int)spike_step(v[i].x, buf);
            unsigned int e1 = (unsigned int)spike_step(v[i].y, buf);
            unsigned int e2 = (unsigned int)spike_step(v[i].z, buf);
            unsigned int e3 = (unsigned int)spike_step(v[i].w, buf);
            ((unsigned int*)sp)[72 + i] = e0 | (e1 << 8) | (e2 << 16) | (e3 << 24);
        }
    }
}

// ---------------- FC: block = (b, t-quad); s5 chunk staged in smem ------------
__global__ void __launch_bounds__(320, 3)
fc_kernel(const unsigned char* __restrict__ s5, const float* __restrict__ wfc,
          float* __restrict__ u_out)
{
    constexpr int NQ = T_STEPS / 4;
    int q = blockIdx.x % NQ;
    int b = blockIdx.x / NQ;
    int t0 = q * 4;

    extern __shared__ float4 s_sm[];
    int tid = threadIdx.y * 32 + threadIdx.x;

    const unsigned char* sb = s5 + (size_t)b * 4096 * TS_U8 + t0;
    for (int c = tid; c < 4096; c += 320) {
        uchar4 cc = *(const uchar4*)&sb[(size_t)c * TS_U8];
        s_sm[c] = make_float4((float)cc.x, (float)cc.y, (float)cc.z, (float)cc.w);
    }
    __syncthreads();

    int o    = threadIdx.y;
    int lane = threadIdx.x;
    const float* wo = wfc + o * 4096;

    float4 acc = make_float4(0.0f, 0.0f, 0.0f, 0.0f);
    for (int c = lane; c < 4096; c += 32) {
        float4 v = s_sm[c];
        float wgt = __ldg(&wo[c]);
        acc.x = fmaf(v.x, wgt, acc.x);
        acc.y = fmaf(v.y, wgt, acc.y);
        acc.z = fmaf(v.z, wgt, acc.z);
        acc.w = fmaf(v.w, wgt, acc.w);
    }
#pragma unroll
    for (int d = 16; d >= 1; d >>= 1) {
        acc.x += __shfl_xor_sync(0xffffffffu, acc.x, d);
        acc.y += __shfl_xor_sync(0xffffffffu, acc.y, d);
        acc.z += __shfl_xor_sync(0xffffffffu, acc.z, d);
        acc.w += __shfl_xor_sync(0xffffffffu, acc.w, d);
    }
    if (lane == 0)
        *(float4*)&u_out[(size_t)(b * 10 + o) * T_STEPS + t0] = acc;
}

// ---------------- final spike on 80 neurons ----------------
__global__ void spike_final_kernel(const float* __restrict__ u, float* __restrict__ out)
{
    int n = threadIdx.x;
    if (n >= 80) return;
    const float4* up = (const float4*)(u + (size_t)n * T_STEPS);
    float4*       sp = (float4*)(out + (size_t)n * T_STEPS);
    float buf[10];
#pragma unroll
    for (int j = 0; j < 10; j++) buf[j] = 0.0f;
    for (int q = 0; q < T_STEPS / 4; q++) {
        float4 uv = up[q];
        float4 ev;
        ev.x = spike_step(uv.x, buf);
        ev.y = spike_step(uv.y, buf);
        ev.z = spike_step(uv.z, buf);
        ev.w = spike_step(uv.w, buf);
        sp[q] = ev;
    }
}

// ---------------- launcher ----------------
extern "C" void kernel_launch(void* const* d_in, const int* in_sizes, int n_in,
                              void* d_out, int out_size)
{
    const float* x   = (const float*)d_in[0];
    const float* w1  = (const float*)d_in[1];
    const float* w2  = (const float*)d_in[2];
    const float* w3  = (const float*)d_in[3];
    const float* wfc = (const float*)d_in[4];
    float* out = (float*)d_out;

    float *A = nullptr, *W = nullptr;
    unsigned char *S = nullptr;
    cudaGetSymbolAddress((void**)&A, g_bufA);
    cudaGetSymbolAddress((void**)&S, g_bufS);
    cudaGetSymbolAddress((void**)&W, g_bufW);
    unsigned char* Au8 = (unsigned char*)A;       // x_u8, later s4
    float* U5 = A + (2u << 20);                    // u5 region (offset 8MB)

    constexpr int SMC1 = 2 * 6 * 36 * C1_TPQ * 16;   // 172800
    constexpr int SMC2 = 16 * 4 * 18 * C2_TPQ * 16;  //  92160
    constexpr int SM3  = 32 * 3 * 10 * 6 * 16;       //  92160
    constexpr int SMF  = 4096 * 16;                  //  65536

    cudaFuncSetAttribute((const void*)conv1sp_kernel,
                         cudaFuncAttributeMaxDynamicSharedMemorySize, SMC1);
    cudaFuncSetAttribute((const void*)conv2sp_kernel,
                         cudaFuncAttributeMaxDynamicSharedMemorySize, SMC2);
    cudaFuncSetAttribute((const void*)conv_kernel<unsigned char,TS_U8,32,8,8,64,8,8,3,1,6,4>,
                         cudaFuncAttributeMaxDynamicSharedMemorySize, SM3);
    cudaFuncSetAttribute((const void*)fc_kernel,
                         cudaFuncAttributeMaxDynamicSharedMemorySize, SMF);

    // prep
    pack_weights_kernel<<<(32000 + 255) / 256, 256>>>(w1, w2, w3, W);
    x_to_u8_kernel<<<(1387200 + 255) / 256, 256>>>(x, Au8);

    // L1 fused: x_u8 (A) -> s2 (S)
    conv1sp_kernel<<<128, 256, SMC1>>>(Au8, W + W1_OFF, S);
    // L2 fused: s2 (S) -> s4 (A, u8; x_u8 dead)
    conv2sp_kernel<<<128, 256, SMC2>>>(S, W + W2_OFF, Au8);
    // L3: conv 32->64 : s4 (A u8) -> u5 (A float, offset 8MB)
    conv_kernel<unsigned char,TS_U8,32,8,8,64,8,8,3,1,6,4>
        <<<8 * 8 * 13, dim3(6, 32), SM3>>>(Au8, W + W3_OFF, U5);
    // spike5: u5 -> s5 (S; s2 dead)
    spike_u8_kernel<<<32768 / 256, 256>>>(U5, S, 32768);
    // FC: s5 (S) -> u6 (A offset 0; s4 dead)
    fc_kernel<<<8 * 75, dim3(32, 10), SMF>>>(S, wfc, A);
    // final spike: u6 -> out
    spike_final_kernel<<<1, 96>>>(A, out);
}

// round 13
// speedup vs baseline: 1.2531x; 1.2531x over previous
#include <cuda_runtime.h>
#include <cstddef>

#define T_STEPS 300
#define TS_U8   304          // padded stride for u8 spike tensors (16B aligned)
#define THETA 10.0f

// ---------------- scratch ----------------
__device__ float g_bufA[39321600];          // float u scratch
__device__ unsigned char g_bufS[9961472];   // u8 spike / u8 input scratch
__device__ float g_bufW[32000];             // packed weights (w1:1280, w2:6144, w3:24576)

__constant__ float c_w[7424];               // packed w1+w2 (constant port)

#define W1_OFF 0
#define W2_OFF 1280
#define W3_OFF 7424

// REF_KERNEL[1..10]: -20*t*exp(1-t), t=1..10 (fp32-rounded from double)
__constant__ float c_refk[10] = {
    -20.0f,
    -14.715177646857693f,
    -8.1201169941967624f,
    -3.9829654694291156f,
    -1.8315638888734179f,
    -0.80855363989025606f,
    -0.34702530473329019f,
    -0.14590111448872260f,
    -0.060383273022452132f,
    -0.024681960817335913f
};

__device__ __forceinline__ float spike_step(float u, float (&buf)[10]) {
    float um = u + buf[0];
    float e = (um >= THETA) ? 1.0f : 0.0f;
#pragma unroll
    for (int j = 0; j < 9; j++) buf[j] = buf[j + 1] + e * c_refk[j];
    buf[9] = e * c_refk[9];
    return e;   // TS = 1 -> amplitude 1
}

// packed 2x fp32 fma (Blackwell FFMA2). Bit-identical to two fmaf's.
__device__ __forceinline__ void ffma2(float2& c, float2 a, float2 b) {
    unsigned long long au = *reinterpret_cast<unsigned long long*>(&a);
    unsigned long long bu = *reinterpret_cast<unsigned long long*>(&b);
    unsigned long long cu = *reinterpret_cast<unsigned long long*>(&c);
    asm("fma.rn.f32x2 %0, %1, %2, %0;" : "+l"(cu) : "l"(au), "l"(bu));
    *reinterpret_cast<unsigned long long*>(&c) = cu;
}

__device__ __forceinline__ void ffma4(float4& c, const float4& a, float w) {
    float2 wv = make_float2(w, w);
    float2 clo = make_float2(c.x, c.y), chi = make_float2(c.z, c.w);
    ffma2(clo, make_float2(a.x, a.y), wv);
    ffma2(chi, make_float2(a.z, a.w), wv);
    c.x = clo.x; c.y = clo.y; c.z = chi.x; c.w = chi.y;
}

__device__ __forceinline__ float f4_get(const float4& v, int i) {
    return i == 0 ? v.x : i == 1 ? v.y : i == 2 ? v.z : v.w;
}

__device__ __forceinline__ float4 load_quad(const float* p) {
    return *(const float4*)p;
}
__device__ __forceinline__ float4 load_quad(const unsigned char* p) {
    uchar4 c = *(const uchar4*)p;
    return make_float4((float)c.x, (float)c.y, (float)c.z, (float)c.w);
}

// ---------------- weight packing: [co][ci][ky][WROW] 16B-aligned rows ---------
__global__ void pack_weights_kernel(const float* __restrict__ w1,
                                    const float* __restrict__ w2,
                                    const float* __restrict__ w3,
                                    float* __restrict__ wp)
{
    int i = blockIdx.x * blockDim.x + threadIdx.x;
    if (i < 1280) {                       // w1: [16][2][5][8]
        int kx = i % 8; int r = i / 8;
        int ky = r % 5; r /= 5;
        int ci = r % 2; int co = r / 2;
        wp[W1_OFF + i] = (kx < 5) ? w1[((co * 2 + ci) * 5 + ky) * 5 + kx] : 0.0f;
    } else if (i < 1280 + 6144) {         // w2: [32][16][3][4]
        int k = i - 1280;
        int kx = k % 4; int r = k / 4;
        int ky = r % 3; r /= 3;
        int ci = r % 16; int co = r / 16;
        wp[W2_OFF + k] = (kx < 3) ? w2[((co * 16 + ci) * 3 + ky) * 3 + kx] : 0.0f;
    } else if (i < 1280 + 6144 + 24576) { // w3: [64][32][3][4]
        int k = i - 1280 - 6144;
        int kx = k % 4; int r = k / 4;
        int ky = r % 3; r /= 3;
        int ci = r % 32; int co = r / 32;
        wp[W3_OFF + k] = (kx < 3) ? w3[((co * 32 + ci) * 3 + ky) * 3 + kx] : 0.0f;
    }
}

// ---------------- input fp32 {0,1} -> u8 (exact) ----------------
__global__ void x_to_u8_kernel(const float* __restrict__ x, unsigned char* __restrict__ y)
{
    int i = blockIdx.x * blockDim.x + threadIdx.x;
    if (i < 1387200) {
        float4 v = ((const float4*)x)[i];
        ((uchar4*)y)[i] = make_uchar4((unsigned char)v.x, (unsigned char)v.y,
                                      (unsigned char)v.z, (unsigned char)v.w);
    }
}

// ---------------- conv (per-timestep 2D conv, T innermost, float4 over time) ---
// block: (b, yo, t-chunk of 4*TPQ steps). threads (TPQ, 32).
// tx owns one timestep quad; ty owns one (co-group, xo-group) item:
// COB=4 output channels x XR=4 x-positions. CWOFF >= 0 -> weights from
// __constant__ c_w (LDC, constant port), else from the packed global array.
template <typename IT, int IN_TS,
          int Ci, int Hi, int Wi, int Co, int Ho, int Wo, int K, int PAD, int TPQ,
          int WROW, int CWOFF>
__global__ void __launch_bounds__(TPQ * 32, 2)
conv_kernel(const IT* __restrict__ in, const float* __restrict__ w,
            float* __restrict__ out)
{
    constexpr int WT  = Wo + K - 1;
    constexpr int XR  = 4;
    constexpr int COB = 4;
    constexpr int XG  = Wo / XR;
    constexpr int CG  = Co / COB;
    static_assert(XG * CG == 32, "one item per ty");
    constexpr int TCH = 4 * TPQ;
    constexpr int NTC = (T_STEPS + TCH - 1) / TCH;
    constexpr int NTH = TPQ * 32;

    extern __shared__ char smraw[];
    float4* sm4 = (float4*)smraw;

    int bid = blockIdx.x;
    int tc  = bid % NTC;
    int yo  = (bid / NTC) % Ho;
    int b   = bid / (NTC * Ho);
    int t0  = tc * TCH;

    int tid = threadIdx.y * TPQ + threadIdx.x;

    // ---- load padded input tile as float4 quads: [Ci][K][WT][TPQ] ----
    constexpr int TILE4 = Ci * K * WT * TPQ;
    for (int flat = tid; flat < TILE4; flat += NTH) {
        int tt = flat % TPQ;
        int r  = flat / TPQ;
        int xw = r % WT; r /= WT;
        int ky = r % K;
        int ci = r / K;
        int xi = xw - PAD;
        int yi = yo - PAD + ky;
        int t  = t0 + 4 * tt;
        float4 v = make_float4(0.0f, 0.0f, 0.0f, 0.0f);
        if (xi >= 0 && xi < Wi && yi >= 0 && yi < Hi && t < T_STEPS)
            v = load_quad(&in[((((size_t)b * Ci + ci) * Hi + yi) * Wi + xi) * IN_TS + t]);
        sm4[flat] = v;
    }
    __syncthreads();

    int tx = threadIdx.x;
    int t  = t0 + 4 * tx;
    int item = threadIdx.y;
    int co0 = (item / XG) * COB;
    int xo0 = (item % XG) * XR;

    float4 acc[COB][XR];
#pragma unroll
    for (int j = 0; j < COB; j++)
#pragma unroll
        for (int r = 0; r < XR; r++) acc[j][r] = make_float4(0.0f, 0.0f, 0.0f, 0.0f);

#pragma unroll 2
    for (int ci = 0; ci < Ci; ci++) {
#pragma unroll
        for (int ky = 0; ky < K; ky++) {
            // input window (shared across all COB channels)
            float4 v[K + XR - 1];
            const float4* sp = &sm4[((ci * K + ky) * WT + xo0) * TPQ + tx];
#pragma unroll
            for (int j = 0; j < K + XR - 1; j++) v[j] = sp[j * TPQ];
            // packed weights: WROW/4 loads per output channel (LDC if constant)
            float4 wq[COB][WROW / 4];
#pragma unroll
            for (int j = 0; j < COB; j++)
#pragma unroll
                for (int p = 0; p < WROW / 4; p++) {
                    int widx = (((co0 + j) * Ci + ci) * K + ky) * WROW + 4 * p;
                    if constexpr (CWOFF >= 0)
                        wq[j][p] = *(const float4*)&c_w[CWOFF + widx];
                    else
                        wq[j][p] = *(const float4*)&w[widx];
                }
            // accumulate: per-output order stays (ci, ky, kx) ascending -> exact
#pragma unroll
            for (int kx = 0; kx < K; kx++)
#pragma unroll
                for (int j = 0; j < COB; j++)
#pragma unroll
                    for (int r = 0; r < XR; r++)
                        ffma4(acc[j][r], v[kx + r], f4_get(wq[j][kx >> 2], kx & 3));
        }
    }

    if (t < T_STEPS) {
#pragma unroll
        for (int j = 0; j < COB; j++)
#pragma unroll
            for (int r = 0; r < XR; r++)
                *(float4*)&out[((((size_t)b * Co + co0 + j) * Ho + yo) * Wo + xo0 + r) * T_STEPS + t]
                    = acc[j][r];
    }
}

// ---------------- fused spike -> 2x2 sum-pool (x11) -> spike, u8 out ----------
// WARP-COOPERATIVE: 4 lanes per pooled neuron; 16-step pipelined.
__device__ __forceinline__ unsigned int pool_quad(float4 uv, float (&bufp)[10],
                                                  float (&bp)[10]) {
    float p0 = spike_step(uv.x, bufp);
    float p1 = spike_step(uv.y, bufp);
    float p2 = spike_step(uv.z, bufp);
    float p3 = spike_step(uv.w, bufp);
    p0 += __shfl_xor_sync(0xffffffffu, p0, 1); p0 += __shfl_xor_sync(0xffffffffu, p0, 2);
    p1 += __shfl_xor_sync(0xffffffffu, p1, 1); p1 += __shfl_xor_sync(0xffffffffu, p1, 2);
    p2 += __shfl_xor_sync(0xffffffffu, p2, 1); p2 += __shfl_xor_sync(0xffffffffu, p2, 2);
    p3 += __shfl_xor_sync(0xffffffffu, p3, 1); p3 += __shfl_xor_sync(0xffffffffu, p3, 2);
    unsigned int e0 = (unsigned int)spike_step(11.0f * p0, bp);
    unsigned int e1 = (unsigned int)spike_step(11.0f * p1, bp);
    unsigned int e2 = (unsigned int)spike_step(11.0f * p2, bp);
    unsigned int e3 = (unsigned int)spike_step(11.0f * p3, bp);
    return e0 | (e1 << 8) | (e2 << 16) | (e3 << 24);
}

__global__ void __launch_bounds__(256)
spikepool_kernel(const float* __restrict__ u, unsigned char* __restrict__ s,
                 int C, int Ho, int Wo)
{
    int idx = blockIdx.x * blockDim.x + threadIdx.x;
    int sub = idx & 3;
    int n   = idx >> 2;
    int total = 8 * C * Ho * Wo;
    if (n >= total) return;
    int x  = n % Wo;
    int y  = (n / Wo) % Ho;
    int cb = n / (Wo * Ho);

    int dy = sub >> 1, dx = sub & 1;
    size_t base = (((size_t)cb * (2 * Ho) + 2 * y + dy) * (2 * Wo) + 2 * x + dx) * T_STEPS;
    const float4* up = (const float4*)(u + base);
    unsigned char* sp = s + (size_t)n * TS_U8;

    float bufp[10], bp[10];
#pragma unroll
    for (int j = 0; j < 10; j++) { bufp[j] = 0.0f; bp[j] = 0.0f; }

    for (int g = 0; g < 18; g++) {
        float4 v[4];
#pragma unroll
        for (int i = 0; i < 4; i++) v[i] = up[g * 4 + i];
        unsigned int wd[4];
#pragma unroll
        for (int i = 0; i < 4; i++) wd[i] = pool_quad(v[i], bufp, bp);
        if (sub == 0)
            ((uint4*)sp)[g] = make_uint4(wd[0], wd[1], wd[2], wd[3]);
    }
    {
        float4 v[3];
#pragma unroll
        for (int i = 0; i < 3; i++) v[i] = up[72 + i];
#pragma unroll
        for (int i = 0; i < 3; i++) {
            unsigned int wd = pool_quad(v[i], bufp, bp);
            if (sub == 0) ((unsigned int*)sp)[72 + i] = wd;
        }
    }
}

// ---------------- spike with u8 output (layer 5), pipelined ----------------
__global__ void __launch_bounds__(256)
spike_u8_kernel(const float* __restrict__ u, unsigned char* __restrict__ s, int nNeurons)
{
    int n = blockIdx.x * blockDim.x + threadIdx.x;
    if (n >= nNeurons) return;
    const float4* up = (const float4*)(u + (size_t)n * T_STEPS);
    unsigned char* sp = s + (size_t)n * TS_U8;
    float buf[10];
#pragma unroll
    for (int j = 0; j < 10; j++) buf[j] = 0.0f;

    for (int g = 0; g < 18; g++) {
        float4 v[4];
#pragma unroll
        for (int i = 0; i < 4; i++) v[i] = up[g * 4 + i];
        unsigned int wd[4];
#pragma unroll
        for (int i = 0; i < 4; i++) {
            unsigned int e0 = (unsigned int)spike_step(v[i].x, buf);
            unsigned int e1 = (unsigned int)spike_step(v[i].y, buf);
            unsigned int e2 = (unsigned int)spike_step(v[i].z, buf);
            unsigned int e3 = (unsigned int)spike_step(v[i].w, buf);
            wd[i] = e0 | (e1 << 8) | (e2 << 16) | (e3 << 24);
        }
        ((uint4*)sp)[g] = make_uint4(wd[0], wd[1], wd[2], wd[3]);
    }
    {
        float4 v[3];
#pragma unroll
        for (int i = 0; i < 3; i++) v[i] = up[72 + i];
#pragma unroll
        for (int i = 0; i < 3; i++) {
            unsigned int e0 = (unsigned int)spike_step(v[i].x, buf);
            unsigned int e1 = (unsigned int)spike_step(v[i].y, buf);
            unsigned int e2 = (unsigned int)spike_step(v[i].z, buf);
            unsigned int e3 = (unsigned int)spike_step(v[i].w, buf);
            ((unsigned int*)sp)[72 + i] = e0 | (e1 << 8) | (e2 << 16) | (e3 << 24);
        }
    }
}

// ---------------- FC: block = (b, t-quad); s5 chunk staged in smem ------------
__global__ void __launch_bounds__(320, 3)
fc_kernel(const unsigned char* __restrict__ s5, const float* __restrict__ wfc,
          float* __restrict__ u_out)
{
    constexpr int NQ = T_STEPS / 4;
    int q = blockIdx.x % NQ;
    int b = blockIdx.x / NQ;
    int t0 = q * 4;

    extern __shared__ float4 s_sm[];
    int tid = threadIdx.y * 32 + threadIdx.x;

    const unsigned char* sb = s5 + (size_t)b * 4096 * TS_U8 + t0;
    for (int c = tid; c < 4096; c += 320) {
        uchar4 cc = *(const uchar4*)&sb[(size_t)c * TS_U8];
        s_sm[c] = make_float4((float)cc.x, (float)cc.y, (float)cc.z, (float)cc.w);
    }
    __syncthreads();

    int o    = threadIdx.y;
    int lane = threadIdx.x;
    const float* wo = wfc + o * 4096;

    float4 acc = make_float4(0.0f, 0.0f, 0.0f, 0.0f);
    for (int c = lane; c < 4096; c += 32) {
        float4 v = s_sm[c];
        float wgt = __ldg(&wo[c]);
        acc.x = fmaf(v.x, wgt, acc.x);
        acc.y = fmaf(v.y, wgt, acc.y);
        acc.z = fmaf(v.z, wgt, acc.z);
        acc.w = fmaf(v.w, wgt, acc.w);
    }
#pragma unroll
    for (int d = 16; d >= 1; d >>= 1) {
        acc.x += __shfl_xor_sync(0xffffffffu, acc.x, d);
        acc.y += __shfl_xor_sync(0xffffffffu, acc.y, d);
        acc.z += __shfl_xor_sync(0xffffffffu, acc.z, d);
        acc.w += __shfl_xor_sync(0xffffffffu, acc.w, d);
    }
    if (lane == 0)
        *(float4*)&u_out[(size_t)(b * 10 + o) * T_STEPS + t0] = acc;
}

// ---------------- final spike on 80 neurons ----------------
__global__ void spike_final_kernel(const float* __restrict__ u, float* __restrict__ out)
{
    int n = threadIdx.x;
    if (n >= 80) return;
    const float4* up = (const float4*)(u + (size_t)n * T_STEPS);
    float4*       sp = (float4*)(out + (size_t)n * T_STEPS);
    float buf[10];
#pragma unroll
    for (int j = 0; j < 10; j++) buf[j] = 0.0f;
    for (int q = 0; q < T_STEPS / 4; q++) {
        float4 uv = up[q];
        float4 ev;
        ev.x = spike_step(uv.x, buf);
        ev.y = spike_step(uv.y, buf);
        ev.z = spike_step(uv.z, buf);
        ev.w = spike_step(uv.w, buf);
        sp[q] = ev;
    }
}

// ---------------- launcher ----------------
extern "C" void kernel_launch(void* const* d_in, const int* in_sizes, int n_in,
                              void* d_out, int out_size)
{
    const float* x   = (const float*)d_in[0];
    const float* w1  = (const float*)d_in[1];
    const float* w2  = (const float*)d_in[2];
    const float* w3  = (const float*)d_in[3];
    const float* wfc = (const float*)d_in[4];
    float* out = (float*)d_out;

    float *A = nullptr, *W = nullptr;
    unsigned char *S = nullptr;
    cudaGetSymbolAddress((void**)&A, g_bufA);
    cudaGetSymbolAddress((void**)&S, g_bufS);
    cudaGetSymbolAddress((void**)&W, g_bufW);

    constexpr int SM1 = 2  * 5 * 36 * 8 * 16;   //  46080  (TPQ=8)
    constexpr int SM2 = 16 * 3 * 18 * 8 * 16;   // 110592  (TPQ=8)
    constexpr int SM3 = 32 * 3 * 10 * 6 * 16;   //  92160  (TPQ=6)
    constexpr int SMF = 4096 * 16;              //  65536

    cudaFuncSetAttribute((const void*)conv_kernel<unsigned char,T_STEPS,2,34,34,16,32,32,5,1,8,8,W1_OFF>,
                         cudaFuncAttributeMaxDynamicSharedMemorySize, SM1);
    cudaFuncSetAttribute((const void*)conv_kernel<unsigned char,TS_U8,16,16,16,32,16,16,3,1,8,4,W2_OFF>,
                         cudaFuncAttributeMaxDynamicSharedMemorySize, SM2);
    cudaFuncSetAttribute((const void*)conv_kernel<unsigned char,TS_U8,32,8,8,64,8,8,3,1,6,4,-1>,
                         cudaFuncAttributeMaxDynamicSharedMemorySize, SM3);
    cudaFuncSetAttribute((const void*)fc_kernel,
                         cudaFuncAttributeMaxDynamicSharedMemorySize, SMF);

    constexpr int NTC8 = 10;   // ceil(300/32)
    constexpr int NTC6 = 13;   // ceil(300/24)

    // prep: pack weights, push w1+w2 to constant, convert input to u8
    pack_weights_kernel<<<(32000 + 255) / 256, 256>>>(w1, w2, w3, W);
    cudaMemcpyToSymbolAsync(c_w, W, 7424 * sizeof(float), 0, cudaMemcpyDeviceToDevice);
    x_to_u8_kernel<<<(1387200 + 255) / 256, 256>>>(x, S);

    // L1: conv 2->16 5x5 pad1 : S(x_u8) -> A (u1)
    conv_kernel<unsigned char,T_STEPS,2,34,34,16,32,32,5,1,8,8,W1_OFF>
        <<<8 * 32 * NTC8, dim3(8, 32), SM1>>>(S, W + W1_OFF, A);
    // spike1 + pool + spike2 fused (4 lanes/neuron): A -> S (s2, u8)
    spikepool_kernel<<<(32768 * 4) / 256, 256>>>(A, S, 16, 16, 16);
    // L2: conv 16->32 3x3 pad1 : S -> A (u3)
    conv_kernel<unsigned char,TS_U8,16,16,16,32,16,16,3,1,8,4,W2_OFF>
        <<<8 * 16 * NTC8, dim3(8, 32), SM2>>>(S, W + W2_OFF, A);
    // spike3 + pool + spike4 fused (4 lanes/neuron): A -> S (s4, u8)
    spikepool_kernel<<<(16384 * 4) / 256, 256>>>(A, S, 32, 8, 8);
    // L3: conv 32->64 3x3 pad1 : S -> A (u5)
    conv_kernel<unsigned char,TS_U8,32,8,8,64,8,8,3,1,6,4,-1>
        <<<8 * 8 * NTC6, dim3(6, 32), SM3>>>(S, W + W3_OFF, A);
    // spike5: A -> S (s5, u8)
    spike_u8_kernel<<<32768 / 256, 256>>>(A, S, 32768);
    // FC: S (s5) -> A (u6)
    fc_kernel<<<8 * 75, dim3(32, 10), SMF>>>(S, wfc, A);
    // final spike: A -> out
    spike_final_kernel<<<1, 96>>>(A, out);
}

// round 14
// speedup vs baseline: 1.3882x; 1.1078x over previous
#include <cuda_runtime.h>
#include <cstddef>

#define T_STEPS 300
#define TS_U8   304          // padded stride for u8 spike tensors (16B aligned)
#define THETA 10.0f

// ---------------- scratch ----------------
__device__ float g_bufA[39321600];          // float u scratch
__device__ unsigned char g_bufS[9961472];   // u8 spike / u8 input scratch
__device__ float g_bufW[32000];             // packed weights (w1:1280, w2:6144, w3:24576)

#define W1_OFF 0
#define W2_OFF 1280
#define W3_OFF 7424

// REF_KERNEL[1..10]: -20*t*exp(1-t), t=1..10 (fp32-rounded from double)
__constant__ float c_refk[10] = {
    -20.0f,
    -14.715177646857693f,
    -8.1201169941967624f,
    -3.9829654694291156f,
    -1.8315638888734179f,
    -0.80855363989025606f,
    -0.34702530473329019f,
    -0.14590111448872260f,
    -0.060383273022452132f,
    -0.024681960817335913f
};

__device__ __forceinline__ float spike_step(float u, float (&buf)[10]) {
    float um = u + buf[0];
    float e = (um >= THETA) ? 1.0f : 0.0f;
#pragma unroll
    for (int j = 0; j < 9; j++) buf[j] = buf[j + 1] + e * c_refk[j];
    buf[9] = e * c_refk[9];
    return e;   // TS = 1 -> amplitude 1
}

// packed 2x fp32 fma (Blackwell FFMA2). Bit-identical to two fmaf's.
__device__ __forceinline__ void ffma2(float2& c, float2 a, float2 b) {
    unsigned long long au = *reinterpret_cast<unsigned long long*>(&a);
    unsigned long long bu = *reinterpret_cast<unsigned long long*>(&b);
    unsigned long long cu = *reinterpret_cast<unsigned long long*>(&c);
    asm("fma.rn.f32x2 %0, %1, %2, %0;" : "+l"(cu) : "l"(au), "l"(bu));
    *reinterpret_cast<unsigned long long*>(&c) = cu;
}

__device__ __forceinline__ void ffma4(float4& c, const float4& a, float w) {
    float2 wv = make_float2(w, w);
    float2 clo = make_float2(c.x, c.y), chi = make_float2(c.z, c.w);
    ffma2(clo, make_float2(a.x, a.y), wv);
    ffma2(chi, make_float2(a.z, a.w), wv);
    c.x = clo.x; c.y = clo.y; c.z = chi.x; c.w = chi.y;
}

__device__ __forceinline__ float f4_get(const float4& v, int i) {
    return i == 0 ? v.x : i == 1 ? v.y : i == 2 ? v.z : v.w;
}

__device__ __forceinline__ float4 load_quad(const float* p) {
    return *(const float4*)p;
}
__device__ __forceinline__ float4 load_quad(const unsigned char* p) {
    uchar4 c = *(const uchar4*)p;
    return make_float4((float)c.x, (float)c.y, (float)c.z, (float)c.w);
}

// ---------------- weight packing: [co][ci][ky][WROW] 16B-aligned rows ---------
__global__ void pack_weights_kernel(const float* __restrict__ w1,
                                    const float* __restrict__ w2,
                                    const float* __restrict__ w3,
                                    float* __restrict__ wp)
{
    int i = blockIdx.x * blockDim.x + threadIdx.x;
    if (i < 1280) {                       // w1: [16][2][5][8]
        int kx = i % 8; int r = i / 8;
        int ky = r % 5; r /= 5;
        int ci = r % 2; int co = r / 2;
        wp[W1_OFF + i] = (kx < 5) ? w1[((co * 2 + ci) * 5 + ky) * 5 + kx] : 0.0f;
    } else if (i < 1280 + 6144) {         // w2: [32][16][3][4]
        int k = i - 1280;
        int kx = k % 4; int r = k / 4;
        int ky = r % 3; r /= 3;
        int ci = r % 16; int co = r / 16;
        wp[W2_OFF + k] = (kx < 3) ? w2[((co * 16 + ci) * 3 + ky) * 3 + kx] : 0.0f;
    } else if (i < 1280 + 6144 + 24576) { // w3: [64][32][3][4]
        int k = i - 1280 - 6144;
        int kx = k % 4; int r = k / 4;
        int ky = r % 3; r /= 3;
        int ci = r % 32; int co = r / 32;
        wp[W3_OFF + k] = (kx < 3) ? w3[((co * 32 + ci) * 3 + ky) * 3 + kx] : 0.0f;
    }
}

// ---------------- input fp32 {0,1} -> u8 (exact) ----------------
__global__ void x_to_u8_kernel(const float* __restrict__ x, unsigned char* __restrict__ y)
{
    int i = blockIdx.x * blockDim.x + threadIdx.x;
    if (i < 1387200) {
        float4 v = ((const float4*)x)[i];
        ((uchar4*)y)[i] = make_uchar4((unsigned char)v.x, (unsigned char)v.y,
                                      (unsigned char)v.z, (unsigned char)v.w);
    }
}

// ---------------- conv1 (K=5): float4 over time, XR=4, COB=4 (R11-proven) -----
template <typename IT, int IN_TS,
          int Ci, int Hi, int Wi, int Co, int Ho, int Wo, int K, int PAD, int TPQ,
          int WROW>
__global__ void __launch_bounds__(TPQ * 32, 2)
conv_kernel(const IT* __restrict__ in, const float* __restrict__ w,
            float* __restrict__ out)
{
    constexpr int WT  = Wo + K - 1;
    constexpr int XR  = 4;
    constexpr int COB = 4;
    constexpr int XG  = Wo / XR;
    constexpr int CG  = Co / COB;
    static_assert(XG * CG == 32, "one item per ty");
    constexpr int TCH = 4 * TPQ;
    constexpr int NTC = (T_STEPS + TCH - 1) / TCH;
    constexpr int NTH = TPQ * 32;

    extern __shared__ char smraw[];
    float4* sm4 = (float4*)smraw;

    int bid = blockIdx.x;
    int tc  = bid % NTC;
    int yo  = (bid / NTC) % Ho;
    int b   = bid / (NTC * Ho);
    int t0  = tc * TCH;

    int tid = threadIdx.y * TPQ + threadIdx.x;

    constexpr int TILE4 = Ci * K * WT * TPQ;
    for (int flat = tid; flat < TILE4; flat += NTH) {
        int tt = flat % TPQ;
        int r  = flat / TPQ;
        int xw = r % WT; r /= WT;
        int ky = r % K;
        int ci = r / K;
        int xi = xw - PAD;
        int yi = yo - PAD + ky;
        int t  = t0 + 4 * tt;
        float4 v = make_float4(0.0f, 0.0f, 0.0f, 0.0f);
        if (xi >= 0 && xi < Wi && yi >= 0 && yi < Hi && t < T_STEPS)
            v = load_quad(&in[((((size_t)b * Ci + ci) * Hi + yi) * Wi + xi) * IN_TS + t]);
        sm4[flat] = v;
    }
    __syncthreads();

    int tx = threadIdx.x;
    int t  = t0 + 4 * tx;
    int item = threadIdx.y;
    int co0 = (item / XG) * COB;
    int xo0 = (item % XG) * XR;

    float4 acc[COB][XR];
#pragma unroll
    for (int j = 0; j < COB; j++)
#pragma unroll
        for (int r = 0; r < XR; r++) acc[j][r] = make_float4(0.0f, 0.0f, 0.0f, 0.0f);

    for (int ci = 0; ci < Ci; ci++) {
#pragma unroll
        for (int ky = 0; ky < K; ky++) {
            float4 v[K + XR - 1];
            const float4* sp = &sm4[((ci * K + ky) * WT + xo0) * TPQ + tx];
#pragma unroll
            for (int j = 0; j < K + XR - 1; j++) v[j] = sp[j * TPQ];
            float4 wq[COB][WROW / 4];
#pragma unroll
            for (int j = 0; j < COB; j++)
#pragma unroll
                for (int p = 0; p < WROW / 4; p++)
                    wq[j][p] = *(const float4*)&w[(((size_t)(co0 + j) * Ci + ci) * K + ky) * WROW + 4 * p];
#pragma unroll
            for (int kx = 0; kx < K; kx++)
#pragma unroll
                for (int j = 0; j < COB; j++)
#pragma unroll
                    for (int r = 0; r < XR; r++)
                        ffma4(acc[j][r], v[kx + r], f4_get(wq[j][kx >> 2], kx & 3));
        }
    }

    if (t < T_STEPS) {
#pragma unroll
        for (int j = 0; j < COB; j++)
#pragma unroll
            for (int r = 0; r < XR; r++)
                *(float4*)&out[((((size_t)b * Co + co0 + j) * Ho + yo) * Wo + xo0 + r) * T_STEPS + t]
                    = acc[j][r];
    }
}

// ---------------- conv 3x3: float2 over time, XR=8, COB=4 ---------------------
// Crossbar relief: per (ci,ky) 10 LDS.64 (2560B, 20cyc) feed 96 FFMA2 (48cyc)
// -> smem no longer co-limits with the fma pipe.
// block: (b, yo, t-chunk of 2*TP steps). threads (TP, 16); ty = one item.
template <int IN_TS, int Ci, int Hi, int Wi, int Co, int Ho, int Wo, int TP>
__global__ void __launch_bounds__(TP * 16, 2)
conv3x3_f2_kernel(const unsigned char* __restrict__ in, const float* __restrict__ w,
                  float* __restrict__ out)
{
    constexpr int K   = 3;
    constexpr int PAD = 1;
    constexpr int WT  = Wo + K - 1;
    constexpr int XR  = 8;
    constexpr int COB = 4;
    constexpr int XG  = Wo / XR;
    constexpr int CG  = Co / COB;
    static_assert(XG * CG == 16, "one item per ty");
    constexpr int TCH = 2 * TP;
    constexpr int NTC = (T_STEPS + TCH - 1) / TCH;
    constexpr int NTH = TP * 16;

    extern __shared__ char smraw[];
    float2* sm2 = (float2*)smraw;

    int bid = blockIdx.x;
    int tc  = bid % NTC;
    int yo  = (bid / NTC) % Ho;
    int b   = bid / (NTC * Ho);
    int t0  = tc * TCH;

    int tid = threadIdx.y * TP + threadIdx.x;

    // ---- load padded tile as float2 pairs [Ci][K][WT][TP]; loader handles a
    // quad (2 adjacent pairs) per iteration -> uchar4 LDG + one STS.128.
    constexpr int TILE4 = Ci * K * WT * (TP / 2);
    for (int flat = tid; flat < TILE4; flat += NTH) {
        int tt = flat % (TP / 2);
        int r  = flat / (TP / 2);
        int xw = r % WT; r /= WT;
        int ky = r % K;
        int ci = r / K;
        int xi = xw - PAD;
        int yi = yo - PAD + ky;
        int t  = t0 + 4 * tt;
        float4 v = make_float4(0.0f, 0.0f, 0.0f, 0.0f);
        if (xi >= 0 && xi < Wi && yi >= 0 && yi < Hi && t < T_STEPS)
            v = load_quad(&in[((((size_t)b * Ci + ci) * Hi + yi) * Wi + xi) * IN_TS + t]);
        *(float4*)&sm2[((size_t)((ci * K + ky) * WT + xw)) * TP + 2 * tt] = v;
    }
    __syncthreads();

    int tx = threadIdx.x;
    int t  = t0 + 2 * tx;
    int item = threadIdx.y;
    int co0 = (item / XG) * COB;
    int xo0 = (item % XG) * XR;

    float2 acc[COB][XR];
#pragma unroll
    for (int j = 0; j < COB; j++)
#pragma unroll
        for (int r = 0; r < XR; r++) acc[j][r] = make_float2(0.0f, 0.0f);

    for (int ci = 0; ci < Ci; ci++) {
#pragma unroll
        for (int ky = 0; ky < K; ky++) {
            // input window: 10 float2 (shared across all COB channels)
            float2 v[K + XR - 1];
            const float2* sp = &sm2[((ci * K + ky) * WT + xo0) * TP + tx];
#pragma unroll
            for (int j = 0; j < K + XR - 1; j++) v[j] = sp[j * TP];
            // one packed float4 weight row per output channel (warp-uniform)
            float4 wk[COB];
#pragma unroll
            for (int j = 0; j < COB; j++)
                wk[j] = *(const float4*)&w[(((size_t)(co0 + j) * Ci + ci) * K + ky) * 4];
            // per-output order stays (ci, ky, kx) ascending -> exact
#pragma unroll
            for (int kx = 0; kx < K; kx++)
#pragma unroll
                for (int j = 0; j < COB; j++) {
                    float wv = f4_get(wk[j], kx);
                    float2 w2 = make_float2(wv, wv);
#pragma unroll
                    for (int r = 0; r < XR; r++)
                        ffma2(acc[j][r], v[kx + r], w2);
                }
        }
    }

    if (t < T_STEPS) {
#pragma unroll
        for (int j = 0; j < COB; j++)
#pragma unroll
            for (int r = 0; r < XR; r++)
                *(float2*)&out[((((size_t)b * Co + co0 + j) * Ho + yo) * Wo + xo0 + r) * T_STEPS + t]
                    = acc[j][r];
    }
}

// ---------------- fused spike -> 2x2 sum-pool (x11) -> spike, u8 out ----------
__device__ __forceinline__ unsigned int pool_quad(float4 uv, float (&bufp)[10],
                                                  float (&bp)[10]) {
    float p0 = spike_step(uv.x, bufp);
    float p1 = spike_step(uv.y, bufp);
    float p2 = spike_step(uv.z, bufp);
    float p3 = spike_step(uv.w, bufp);
    p0 += __shfl_xor_sync(0xffffffffu, p0, 1); p0 += __shfl_xor_sync(0xffffffffu, p0, 2);
    p1 += __shfl_xor_sync(0xffffffffu, p1, 1); p1 += __shfl_xor_sync(0xffffffffu, p1, 2);
    p2 += __shfl_xor_sync(0xffffffffu, p2, 1); p2 += __shfl_xor_sync(0xffffffffu, p2, 2);
    p3 += __shfl_xor_sync(0xffffffffu, p3, 1); p3 += __shfl_xor_sync(0xffffffffu, p3, 2);
    unsigned int e0 = (unsigned int)spike_step(11.0f * p0, bp);
    unsigned int e1 = (unsigned int)spike_step(11.0f * p1, bp);
    unsigned int e2 = (unsigned int)spike_step(11.0f * p2, bp);
    unsigned int e3 = (unsigned int)spike_step(11.0f * p3, bp);
    return e0 | (e1 << 8) | (e2 << 16) | (e3 << 24);
}

__global__ void __launch_bounds__(256)
spikepool_kernel(const float* __restrict__ u, unsigned char* __restrict__ s,
                 int C, int Ho, int Wo)
{
    int idx = blockIdx.x * blockDim.x + threadIdx.x;
    int sub = idx & 3;
    int n   = idx >> 2;
    int total = 8 * C * Ho * Wo;
    if (n >= total) return;
    int x  = n % Wo;
    int y  = (n / Wo) % Ho;
    int cb = n / (Wo * Ho);

    int dy = sub >> 1, dx = sub & 1;
    size_t base = (((size_t)cb * (2 * Ho) + 2 * y + dy) * (2 * Wo) + 2 * x + dx) * T_STEPS;
    const float4* up = (const float4*)(u + base);
    unsigned char* sp = s + (size_t)n * TS_U8;

    float bufp[10], bp[10];
#pragma unroll
    for (int j = 0; j < 10; j++) { bufp[j] = 0.0f; bp[j] = 0.0f; }

    for (int g = 0; g < 18; g++) {
        float4 v[4];
#pragma unroll
        for (int i = 0; i < 4; i++) v[i] = up[g * 4 + i];
        unsigned int wd[4];
#pragma unroll
        for (int i = 0; i < 4; i++) wd[i] = pool_quad(v[i], bufp, bp);
        if (sub == 0)
            ((uint4*)sp)[g] = make_uint4(wd[0], wd[1], wd[2], wd[3]);
    }
    {
        float4 v[3];
#pragma unroll
        for (int i = 0; i < 3; i++) v[i] = up[72 + i];
#pragma unroll
        for (int i = 0; i < 3; i++) {
            unsigned int wd = pool_quad(v[i], bufp, bp);
            if (sub == 0) ((unsigned int*)sp)[72 + i] = wd;
        }
    }
}

// ---------------- spike with u8 output (layer 5), pipelined ----------------
__global__ void __launch_bounds__(256)
spike_u8_kernel(const float* __restrict__ u, unsigned char* __restrict__ s, int nNeurons)
{
    int n = blockIdx.x * blockDim.x + threadIdx.x;
    if (n >= nNeurons) return;
    const float4* up = (const float4*)(u + (size_t)n * T_STEPS);
    unsigned char* sp = s + (size_t)n * TS_U8;
    float buf[10];
#pragma unroll
    for (int j = 0; j < 10; j++) buf[j] = 0.0f;

    for (int g = 0; g < 18; g++) {
        float4 v[4];
#pragma unroll
        for (int i = 0; i < 4; i++) v[i] = up[g * 4 + i];
        unsigned int wd[4];
#pragma unroll
        for (int i = 0; i < 4; i++) {
            unsigned int e0 = (unsigned int)spike_step(v[i].x, buf);
            unsigned int e1 = (unsigned int)spike_step(v[i].y, buf);
            unsigned int e2 = (unsigned int)spike_step(v[i].z, buf);
            unsigned int e3 = (unsigned int)spike_step(v[i].w, buf);
            wd[i] = e0 | (e1 << 8) | (e2 << 16) | (e3 << 24);
        }
        ((uint4*)sp)[g] = make_uint4(wd[0], wd[1], wd[2], wd[3]);
    }
    {
        float4 v[3];
#pragma unroll
        for (int i = 0; i < 3; i++) v[i] = up[72 + i];
#pragma unroll
        for (int i = 0; i < 3; i++) {
            unsigned int e0 = (unsigned int)spike_step(v[i].x, buf);
            unsigned int e1 = (unsigned int)spike_step(v[i].y, buf);
            unsigned int e2 = (unsigned int)spike_step(v[i].z, buf);
            unsigned int e3 = (unsigned int)spike_step(v[i].w, buf);
            ((unsigned int*)sp)[72 + i] = e0 | (e1 << 8) | (e2 << 16) | (e3 << 24);
        }
    }
}

// ---------------- FC: block = (b, t-quad); s5 chunk staged in smem ------------
__global__ void __launch_bounds__(320, 3)
fc_kernel(const unsigned char* __restrict__ s5, const float* __restrict__ wfc,
          float* __restrict__ u_out)
{
    constexpr int NQ = T_STEPS / 4;
    int q = blockIdx.x % NQ;
    int b = blockIdx.x / NQ;
    int t0 = q * 4;

    extern __shared__ float4 s_sm[];
    int tid = threadIdx.y * 32 + threadIdx.x;

    const unsigned char* sb = s5 + (size_t)b * 4096 * TS_U8 + t0;
    for (int c = tid; c < 4096; c += 320) {
        uchar4 cc = *(const uchar4*)&sb[(size_t)c * TS_U8];
        s_sm[c] = make_float4((float)cc.x, (float)cc.y, (float)cc.z, (float)cc.w);
    }
    __syncthreads();

    int o    = threadIdx.y;
    int lane = threadIdx.x;
    const float* wo = wfc + o * 4096;

    float4 acc = make_float4(0.0f, 0.0f, 0.0f, 0.0f);
    for (int c = lane; c < 4096; c += 32) {
        float4 v = s_sm[c];
        float wgt = __ldg(&wo[c]);
        acc.x = fmaf(v.x, wgt, acc.x);
        acc.y = fmaf(v.y, wgt, acc.y);
        acc.z = fmaf(v.z, wgt, acc.z);
        acc.w = fmaf(v.w, wgt, acc.w);
    }
#pragma unroll
    for (int d = 16; d >= 1; d >>= 1) {
        acc.x += __shfl_xor_sync(0xffffffffu, acc.x, d);
        acc.y += __shfl_xor_sync(0xffffffffu, acc.y, d);
        acc.z += __shfl_xor_sync(0xffffffffu, acc.z, d);
        acc.w += __shfl_xor_sync(0xffffffffu, acc.w, d);
    }
    if (lane == 0)
        *(float4*)&u_out[(size_t)(b * 10 + o) * T_STEPS + t0] = acc;
}

// ---------------- final spike on 80 neurons ----------------
__global__ void spike_final_kernel(const float* __restrict__ u, float* __restrict__ out)
{
    int n = threadIdx.x;
    if (n >= 80) return;
    const float4* up = (const float4*)(u + (size_t)n * T_STEPS);
    float4*       sp = (float4*)(out + (size_t)n * T_STEPS);
    float buf[10];
#pragma unroll
    for (int j = 0; j < 10; j++) buf[j] = 0.0f;
    for (int q = 0; q < T_STEPS / 4; q++) {
        float4 uv = up[q];
        float4 ev;
        ev.x = spike_step(uv.x, buf);
        ev.y = spike_step(uv.y, buf);
        ev.z = spike_step(uv.z, buf);
        ev.w = spike_step(uv.w, buf);
        sp[q] = ev;
    }
}

// ---------------- launcher ----------------
extern "C" void kernel_launch(void* const* d_in, const int* in_sizes, int n_in,
                              void* d_out, int out_size)
{
    const float* x   = (const float*)d_in[0];
    const float* w1  = (const float*)d_in[1];
    const float* w2  = (const float*)d_in[2];
    const float* w3  = (const float*)d_in[3];
    const float* wfc = (const float*)d_in[4];
    float* out = (float*)d_out;

    float *A = nullptr, *W = nullptr;
    unsigned char *S = nullptr;
    cudaGetSymbolAddress((void**)&A, g_bufA);
    cudaGetSymbolAddress((void**)&S, g_bufS);
    cudaGetSymbolAddress((void**)&W, g_bufW);

    constexpr int SM1 = 2  * 5 * 36 * 8 * 16;    //  46080  (TPQ=8, float4)
    constexpr int SM2 = 16 * 3 * 18 * 16 * 8;    // 110592  (TP=16, float2)
    constexpr int SM3 = 32 * 3 * 10 * 12 * 8;    //  92160  (TP=12, float2)
    constexpr int SMF = 4096 * 16;               //  65536

    cudaFuncSetAttribute((const void*)conv_kernel<unsigned char,T_STEPS,2,34,34,16,32,32,5,1,8,8>,
                         cudaFuncAttributeMaxDynamicSharedMemorySize, SM1);
    cudaFuncSetAttribute((const void*)conv3x3_f2_kernel<TS_U8,16,16,16,32,16,16,16>,
                         cudaFuncAttributeMaxDynamicSharedMemorySize, SM2);
    cudaFuncSetAttribute((const void*)conv3x3_f2_kernel<TS_U8,32,8,8,64,8,8,12>,
                         cudaFuncAttributeMaxDynamicSharedMemorySize, SM3);
    cudaFuncSetAttribute((const void*)fc_kernel,
                         cudaFuncAttributeMaxDynamicSharedMemorySize, SMF);

    // prep: pack weights, convert input to u8
    pack_weights_kernel<<<(32000 + 255) / 256, 256>>>(w1, w2, w3, W);
    x_to_u8_kernel<<<(1387200 + 255) / 256, 256>>>(x, S);

    // L1: conv 2->16 5x5 pad1 : S(x_u8) -> A (u1)
    conv_kernel<unsigned char,T_STEPS,2,34,34,16,32,32,5,1,8,8>
        <<<8 * 32 * 10, dim3(8, 32), SM1>>>(S, W + W1_OFF, A);
    // spike1 + pool + spike2 fused (4 lanes/neuron): A -> S (s2, u8)
    spikepool_kernel<<<(32768 * 4) / 256, 256>>>(A, S, 16, 16, 16);
    // L2: conv 16->32 3x3 pad1 : S -> A (u3)   [float2/XR8 path]
    conv3x3_f2_kernel<TS_U8,16,16,16,32,16,16,16>
        <<<8 * 16 * 10, dim3(16, 16), SM2>>>(S, W + W2_OFF, A);
    // spike3 + pool + spike4 fused (4 lanes/neuron): A -> S (s4, u8)
    spikepool_kernel<<<(16384 * 4) / 256, 256>>>(A, S, 32, 8, 8);
    // L3: conv 32->64 3x3 pad1 : S -> A (u5)   [float2/XR8 path]
    conv3x3_f2_kernel<TS_U8,32,8,8,64,8,8,12>
        <<<8 * 8 * 13, dim3(12, 16), SM3>>>(S, W + W3_OFF, A);
    // spike5: A -> S (s5, u8)
    spike_u8_kernel<<<32768 / 256, 256>>>(A, S, 32768);
    // FC: S (s5) -> A (u6)
    fc_kernel<<<8 * 75, dim3(32, 10), SMF>>>(S, wfc, A);
    // final spike: A -> out
    spike_final_kernel<<<1, 96>>>(A, out);
}

// round 15
// speedup vs baseline: 1.4275x; 1.0283x over previous
#include <cuda_runtime.h>
#include <cstddef>

#define T_STEPS 300
#define TS_U8   304          // padded stride for u8 spike tensors (16B aligned)
#define UQ_STR4 304          // float4 stride per pooled-neuron row (4864B, 128B-aligned)
#define THETA 10.0f

// ---------------- scratch ----------------
__device__ float g_bufA[40000000];          // float u scratch
__device__ unsigned char g_bufS[9961472];   // u8 spike / u8 input scratch
__device__ float g_bufW[32000];             // packed weights (w1:1280, w2:6144, w3:24576)

#define W1_OFF 0
#define W2_OFF 1280
#define W3_OFF 7424

// REF_KERNEL[1..10]: -20*t*exp(1-t), t=1..10 (fp32-rounded from double)
__constant__ float c_refk[10] = {
    -20.0f,
    -14.715177646857693f,
    -8.1201169941967624f,
    -3.9829654694291156f,
    -1.8315638888734179f,
    -0.80855363989025606f,
    -0.34702530473329019f,
    -0.14590111448872260f,
    -0.060383273022452132f,
    -0.024681960817335913f
};

__device__ __forceinline__ float spike_step(float u, float (&buf)[10]) {
    float um = u + buf[0];
    float e = (um >= THETA) ? 1.0f : 0.0f;
#pragma unroll
    for (int j = 0; j < 9; j++) buf[j] = buf[j + 1] + e * c_refk[j];
    buf[9] = e * c_refk[9];
    return e;   // TS = 1 -> amplitude 1
}

// packed 2x fp32 fma (Blackwell FFMA2). Bit-identical to two fmaf's.
__device__ __forceinline__ void ffma2(float2& c, float2 a, float2 b) {
    unsigned long long au = *reinterpret_cast<unsigned long long*>(&a);
    unsigned long long bu = *reinterpret_cast<unsigned long long*>(&b);
    unsigned long long cu = *reinterpret_cast<unsigned long long*>(&c);
    asm("fma.rn.f32x2 %0, %1, %2, %0;" : "+l"(cu) : "l"(au), "l"(bu));
    *reinterpret_cast<unsigned long long*>(&c) = cu;
}

__device__ __forceinline__ void ffma4(float4& c, const float4& a, float w) {
    float2 wv = make_float2(w, w);
    float2 clo = make_float2(c.x, c.y), chi = make_float2(c.z, c.w);
    ffma2(clo, make_float2(a.x, a.y), wv);
    ffma2(chi, make_float2(a.z, a.w), wv);
    c.x = clo.x; c.y = clo.y; c.z = chi.x; c.w = chi.y;
}

__device__ __forceinline__ float f4_get(const float4& v, int i) {
    return i == 0 ? v.x : i == 1 ? v.y : i == 2 ? v.z : v.w;
}

__device__ __forceinline__ float4 load_quad(const float* p) {
    return *(const float4*)p;
}
__device__ __forceinline__ float4 load_quad(const unsigned char* p) {
    uchar4 c = *(const uchar4*)p;
    return make_float4((float)c.x, (float)c.y, (float)c.z, (float)c.w);
}

// ---------------- weight packing: [co][ci][ky][WROW] 16B-aligned rows ---------
__global__ void pack_weights_kernel(const float* __restrict__ w1,
                                    const float* __restrict__ w2,
                                    const float* __restrict__ w3,
                                    float* __restrict__ wp)
{
    int i = blockIdx.x * blockDim.x + threadIdx.x;
    if (i < 1280) {                       // w1: [16][2][5][8]
        int kx = i % 8; int r = i / 8;
        int ky = r % 5; r /= 5;
        int ci = r % 2; int co = r / 2;
        wp[W1_OFF + i] = (kx < 5) ? w1[((co * 2 + ci) * 5 + ky) * 5 + kx] : 0.0f;
    } else if (i < 1280 + 6144) {         // w2: [32][16][3][4]
        int k = i - 1280;
        int kx = k % 4; int r = k / 4;
        int ky = r % 3; r /= 3;
        int ci = r % 16; int co = r / 16;
        wp[W2_OFF + k] = (kx < 3) ? w2[((co * 16 + ci) * 3 + ky) * 3 + kx] : 0.0f;
    } else if (i < 1280 + 6144 + 24576) { // w3: [64][32][3][4]
        int k = i - 1280 - 6144;
        int kx = k % 4; int r = k / 4;
        int ky = r % 3; r /= 3;
        int ci = r % 32; int co = r / 32;
        wp[W3_OFF + k] = (kx < 3) ? w3[((co * 32 + ci) * 3 + ky) * 3 + kx] : 0.0f;
    }
}

// ---------------- input fp32 {0,1} -> u8 (exact) ----------------
__global__ void x_to_u8_kernel(const float* __restrict__ x, unsigned char* __restrict__ y)
{
    int i = blockIdx.x * blockDim.x + threadIdx.x;
    if (i < 1387200) {
        float4 v = ((const float4*)x)[i];
        ((uchar4*)y)[i] = make_uchar4((unsigned char)v.x, (unsigned char)v.y,
                                      (unsigned char)v.z, (unsigned char)v.w);
    }
}

// ---------------- conv (R11-proven): float4 over time, XR=4, COB=4 ------------
// POOLQ: write u in interleaved pooled layout [n][q][sub] float4 (n = pooled
// neuron, sub = (y&1)*2 + (x&1)) so spikepool's 4-lane groups read contiguous.
template <typename IT, int IN_TS,
          int Ci, int Hi, int Wi, int Co, int Ho, int Wo, int K, int PAD, int TPQ,
          int WROW, bool POOLQ>
__global__ void __launch_bounds__(TPQ * 32, 2)
conv_kernel(const IT* __restrict__ in, const float* __restrict__ w,
            float* __restrict__ out)
{
    constexpr int WT  = Wo + K - 1;
    constexpr int XR  = 4;
    constexpr int COB = 4;
    constexpr int XG  = Wo / XR;
    constexpr int CG  = Co / COB;
    static_assert(XG * CG == 32, "one item per ty");
    constexpr int TCH = 4 * TPQ;
    constexpr int NTC = (T_STEPS + TCH - 1) / TCH;
    constexpr int NTH = TPQ * 32;

    extern __shared__ char smraw[];
    float4* sm4 = (float4*)smraw;

    int bid = blockIdx.x;
    int tc  = bid % NTC;
    int yo  = (bid / NTC) % Ho;
    int b   = bid / (NTC * Ho);
    int t0  = tc * TCH;

    int tid = threadIdx.y * TPQ + threadIdx.x;

    constexpr int TILE4 = Ci * K * WT * TPQ;
    for (int flat = tid; flat < TILE4; flat += NTH) {
        int tt = flat % TPQ;
        int r  = flat / TPQ;
        int xw = r % WT; r /= WT;
        int ky = r % K;
        int ci = r / K;
        int xi = xw - PAD;
        int yi = yo - PAD + ky;
        int t  = t0 + 4 * tt;
        float4 v = make_float4(0.0f, 0.0f, 0.0f, 0.0f);
        if (xi >= 0 && xi < Wi && yi >= 0 && yi < Hi && t < T_STEPS)
            v = load_quad(&in[((((size_t)b * Ci + ci) * Hi + yi) * Wi + xi) * IN_TS + t]);
        sm4[flat] = v;
    }
    __syncthreads();

    int tx = threadIdx.x;
    int t  = t0 + 4 * tx;
    int item = threadIdx.y;
    int co0 = (item / XG) * COB;
    int xo0 = (item % XG) * XR;

    float4 acc[COB][XR];
#pragma unroll
    for (int j = 0; j < COB; j++)
#pragma unroll
        for (int r = 0; r < XR; r++) acc[j][r] = make_float4(0.0f, 0.0f, 0.0f, 0.0f);

    for (int ci = 0; ci < Ci; ci++) {
#pragma unroll
        for (int ky = 0; ky < K; ky++) {
            float4 v[K + XR - 1];
            const float4* sp = &sm4[((ci * K + ky) * WT + xo0) * TPQ + tx];
#pragma unroll
            for (int j = 0; j < K + XR - 1; j++) v[j] = sp[j * TPQ];
            float4 wq[COB][WROW / 4];
#pragma unroll
            for (int j = 0; j < COB; j++)
#pragma unroll
                for (int p = 0; p < WROW / 4; p++)
                    wq[j][p] = *(const float4*)&w[(((size_t)(co0 + j) * Ci + ci) * K + ky) * WROW + 4 * p];
#pragma unroll
            for (int kx = 0; kx < K; kx++)
#pragma unroll
                for (int j = 0; j < COB; j++)
#pragma unroll
                    for (int r = 0; r < XR; r++)
                        ffma4(acc[j][r], v[kx + r], f4_get(wq[j][kx >> 2], kx & 3));
        }
    }

    if (t < T_STEPS) {
        if constexpr (POOLQ) {
            int q = t >> 2;
#pragma unroll
            for (int j = 0; j < COB; j++)
#pragma unroll
                for (int r = 0; r < XR; r++) {
                    int co = co0 + j, x = xo0 + r;
                    int n = (((b * Co + co) * (Ho >> 1) + (yo >> 1)) * (Wo >> 1)) + (x >> 1);
                    int sub = ((yo & 1) << 1) | (x & 1);
                    ((float4*)out)[(size_t)n * UQ_STR4 + q * 4 + sub] = acc[j][r];
                }
        } else {
#pragma unroll
            for (int j = 0; j < COB; j++)
#pragma unroll
                for (int r = 0; r < XR; r++)
                    *(float4*)&out[((((size_t)b * Co + co0 + j) * Ho + yo) * Wo + xo0 + r) * T_STEPS + t]
                        = acc[j][r];
        }
    }
}

// ---------------- fused spike -> 2x2 sum-pool (x11) -> spike, u8 out ----------
// Input is the interleaved pooled layout: lane sub reads [n][q][sub] -> 4-lane
// groups read contiguous 64B per (g,i). 128-thread blocks for SM spread.
__device__ __forceinline__ unsigned int pool_quad(float4 uv, float (&bufp)[10],
                                                  float (&bp)[10]) {
    float p0 = spike_step(uv.x, bufp);
    float p1 = spike_step(uv.y, bufp);
    float p2 = spike_step(uv.z, bufp);
    float p3 = spike_step(uv.w, bufp);
    p0 += __shfl_xor_sync(0xffffffffu, p0, 1); p0 += __shfl_xor_sync(0xffffffffu, p0, 2);
    p1 += __shfl_xor_sync(0xffffffffu, p1, 1); p1 += __shfl_xor_sync(0xffffffffu, p1, 2);
    p2 += __shfl_xor_sync(0xffffffffu, p2, 1); p2 += __shfl_xor_sync(0xffffffffu, p2, 2);
    p3 += __shfl_xor_sync(0xffffffffu, p3, 1); p3 += __shfl_xor_sync(0xffffffffu, p3, 2);
    unsigned int e0 = (unsigned int)spike_step(11.0f * p0, bp);
    unsigned int e1 = (unsigned int)spike_step(11.0f * p1, bp);
    unsigned int e2 = (unsigned int)spike_step(11.0f * p2, bp);
    unsigned int e3 = (unsigned int)spike_step(11.0f * p3, bp);
    return e0 | (e1 << 8) | (e2 << 16) | (e3 << 24);
}

__global__ void __launch_bounds__(128)
spikepool_kernel(const float* __restrict__ u, unsigned char* __restrict__ s, int total)
{
    int idx = blockIdx.x * 128 + threadIdx.x;
    int sub = idx & 3;
    int n   = idx >> 2;
    if (n >= total) return;

    const float4* up = (const float4*)u + (size_t)n * UQ_STR4 + sub;
    unsigned char* sp = s + (size_t)n * TS_U8;

    float bufp[10], bp[10];
#pragma unroll
    for (int j = 0; j < 10; j++) { bufp[j] = 0.0f; bp[j] = 0.0f; }

    for (int g = 0; g < 18; g++) {
        float4 v[4];
#pragma unroll
        for (int i = 0; i < 4; i++) v[i] = up[(g * 4 + i) * 4];
        unsigned int wd[4];
#pragma unroll
        for (int i = 0; i < 4; i++) wd[i] = pool_quad(v[i], bufp, bp);
        if (sub == 0)
            ((uint4*)sp)[g] = make_uint4(wd[0], wd[1], wd[2], wd[3]);
    }
    {
        float4 v[3];
#pragma unroll
        for (int i = 0; i < 3; i++) v[i] = up[(72 + i) * 4];
#pragma unroll
        for (int i = 0; i < 3; i++) {
            unsigned int wd = pool_quad(v[i], bufp, bp);
            if (sub == 0) ((unsigned int*)sp)[72 + i] = wd;
        }
    }
}

// ---------------- spike with u8 output (layer 5), 64-thr blocks ----------------
__global__ void __launch_bounds__(64)
spike_u8_kernel(const float* __restrict__ u, unsigned char* __restrict__ s, int nNeurons)
{
    int n = blockIdx.x * 64 + threadIdx.x;
    if (n >= nNeurons) return;
    const float4* up = (const float4*)(u + (size_t)n * T_STEPS);
    unsigned char* sp = s + (size_t)n * TS_U8;
    float buf[10];
#pragma unroll
    for (int j = 0; j < 10; j++) buf[j] = 0.0f;

    for (int g = 0; g < 18; g++) {
        float4 v[4];
#pragma unroll
        for (int i = 0; i < 4; i++) v[i] = up[g * 4 + i];
        unsigned int wd[4];
#pragma unroll
        for (int i = 0; i < 4; i++) {
            unsigned int e0 = (unsigned int)spike_step(v[i].x, buf);
            unsigned int e1 = (unsigned int)spike_step(v[i].y, buf);
            unsigned int e2 = (unsigned int)spike_step(v[i].z, buf);
            unsigned int e3 = (unsigned int)spike_step(v[i].w, buf);
            wd[i] = e0 | (e1 << 8) | (e2 << 16) | (e3 << 24);
        }
        ((uint4*)sp)[g] = make_uint4(wd[0], wd[1], wd[2], wd[3]);
    }
    {
        float4 v[3];
#pragma unroll
        for (int i = 0; i < 3; i++) v[i] = up[72 + i];
#pragma unroll
        for (int i = 0; i < 3; i++) {
            unsigned int e0 = (unsigned int)spike_step(v[i].x, buf);
            unsigned int e1 = (unsigned int)spike_step(v[i].y, buf);
            unsigned int e2 = (unsigned int)spike_step(v[i].z, buf);
            unsigned int e3 = (unsigned int)spike_step(v[i].w, buf);
            ((unsigned int*)sp)[72 + i] = e0 | (e1 << 8) | (e2 << 16) | (e3 << 24);
        }
    }
}

// ---------------- FC: block = (b, t-quad); s5 chunk staged in smem ------------
__global__ void __launch_bounds__(320, 3)
fc_kernel(const unsigned char* __restrict__ s5, const float* __restrict__ wfc,
          float* __restrict__ u_out)
{
    constexpr int NQ = T_STEPS / 4;
    int q = blockIdx.x % NQ;
    int b = blockIdx.x / NQ;
    int t0 = q * 4;

    extern __shared__ float4 s_sm[];
    int tid = threadIdx.y * 32 + threadIdx.x;

    const unsigned char* sb = s5 + (size_t)b * 4096 * TS_U8 + t0;
    for (int c = tid; c < 4096; c += 320) {
        uchar4 cc = *(const uchar4*)&sb[(size_t)c * TS_U8];
        s_sm[c] = make_float4((float)cc.x, (float)cc.y, (float)cc.z, (float)cc.w);
    }
    __syncthreads();

    int o    = threadIdx.y;
    int lane = threadIdx.x;
    const float* wo = wfc + o * 4096;

    float4 acc = make_float4(0.0f, 0.0f, 0.0f, 0.0f);
    for (int c = lane; c < 4096; c += 32) {
        float4 v = s_sm[c];
        float wgt = __ldg(&wo[c]);
        acc.x = fmaf(v.x, wgt, acc.x);
        acc.y = fmaf(v.y, wgt, acc.y);
        acc.z = fmaf(v.z, wgt, acc.z);
        acc.w = fmaf(v.w, wgt, acc.w);
    }
#pragma unroll
    for (int d = 16; d >= 1; d >>= 1) {
        acc.x += __shfl_xor_sync(0xffffffffu, acc.x, d);
        acc.y += __shfl_xor_sync(0xffffffffu, acc.y, d);
        acc.z += __shfl_xor_sync(0xffffffffu, acc.z, d);
        acc.w += __shfl_xor_sync(0xffffffffu, acc.w, d);
    }
    if (lane == 0)
        *(float4*)&u_out[(size_t)(b * 10 + o) * T_STEPS + t0] = acc;
}

// ---------------- final spike on 80 neurons ----------------
__global__ void spike_final_kernel(const float* __restrict__ u, float* __restrict__ out)
{
    int n = threadIdx.x;
    if (n >= 80) return;
    const float4* up = (const float4*)(u + (size_t)n * T_STEPS);
    float4*       sp = (float4*)(out + (size_t)n * T_STEPS);
    float buf[10];
#pragma unroll
    for (int j = 0; j < 10; j++) buf[j] = 0.0f;
    for (int q = 0; q < T_STEPS / 4; q++) {
        float4 uv = up[q];
        float4 ev;
        ev.x = spike_step(uv.x, buf);
        ev.y = spike_step(uv.y, buf);
        ev.z = spike_step(uv.z, buf);
        ev.w = spike_step(uv.w, buf);
        sp[q] = ev;
    }
}

// ---------------- launcher ----------------
extern "C" void kernel_launch(void* const* d_in, const int* in_sizes, int n_in,
                              void* d_out, int out_size)
{
    const float* x   = (const float*)d_in[0];
    const float* w1  = (const float*)d_in[1];
    const float* w2  = (const float*)d_in[2];
    const float* w3  = (const float*)d_in[3];
    const float* wfc = (const float*)d_in[4];
    float* out = (float*)d_out;

    float *A = nullptr, *W = nullptr;
    unsigned char *S = nullptr;
    cudaGetSymbolAddress((void**)&A, g_bufA);
    cudaGetSymbolAddress((void**)&S, g_bufS);
    cudaGetSymbolAddress((void**)&W, g_bufW);

    constexpr int SM1 = 2  * 5 * 36 * 8 * 16;   //  46080  (TPQ=8)
    constexpr int SM2 = 16 * 3 * 18 * 8 * 16;   // 110592  (TPQ=8)
    constexpr int SM3 = 32 * 3 * 10 * 6 * 16;   //  92160  (TPQ=6)
    constexpr int SMF = 4096 * 16;              //  65536

    cudaFuncSetAttribute((const void*)conv_kernel<unsigned char,T_STEPS,2,34,34,16,32,32,5,1,8,8,true>,
                         cudaFuncAttributeMaxDynamicSharedMemorySize, SM1);
    cudaFuncSetAttribute((const void*)conv_kernel<unsigned char,TS_U8,16,16,16,32,16,16,3,1,8,4,true>,
                         cudaFuncAttributeMaxDynamicSharedMemorySize, SM2);
    cudaFuncSetAttribute((const void*)conv_kernel<unsigned char,TS_U8,32,8,8,64,8,8,3,1,6,4,false>,
                         cudaFuncAttributeMaxDynamicSharedMemorySize, SM3);
    cudaFuncSetAttribute((const void*)fc_kernel,
                         cudaFuncAttributeMaxDynamicSharedMemorySize, SMF);

    constexpr int NTC8 = 10;   // ceil(300/32)
    constexpr int NTC6 = 13;   // ceil(300/24)

    // prep: pack weights, convert input to u8
    pack_weights_kernel<<<(32000 + 255) / 256, 256>>>(w1, w2, w3, W);
    x_to_u8_kernel<<<(1387200 + 255) / 256, 256>>>(x, S);

    // L1: conv 2->16 5x5 pad1 : S(x_u8) -> A (u1, interleaved pooled layout)
    conv_kernel<unsigned char,T_STEPS,2,34,34,16,32,32,5,1,8,8,true>
        <<<8 * 32 * NTC8, dim3(8, 32), SM1>>>(S, W + W1_OFF, A);
    // spike1 + pool + spike2 fused (4 lanes/neuron): A -> S (s2, u8)
    spikepool_kernel<<<(32768 * 4) / 128, 128>>>(A, S, 32768);
    // L2: conv 16->32 3x3 pad1 : S -> A (u3, interleaved pooled layout)
    conv_kernel<unsigned char,TS_U8,16,16,16,32,16,16,3,1,8,4,true>
        <<<8 * 16 * NTC8, dim3(8, 32), SM2>>>(S, W + W2_OFF, A);
    // spike3 + pool + spike4 fused (4 lanes/neuron): A -> S (s4, u8)
    spikepool_kernel<<<(16384 * 4) / 128, 128>>>(A, S, 16384);
    // L3: conv 32->64 3x3 pad1 : S -> A (u5, standard layout)
    conv_kernel<unsigned char,TS_U8,32,8,8,64,8,8,3,1,6,4,false>
        <<<8 * 8 * NTC6, dim3(6, 32), SM3>>>(S, W + W3_OFF, A);
    // spike5: A -> S (s5, u8)
    spike_u8_kernel<<<32768 / 64, 64>>>(A, S, 32768);
    // FC: S (s5) -> A (u6)
    fc_kernel<<<8 * 75, dim3(32, 10), SMF>>>(S, wfc, A);
    // final spike: A -> out
    spike_final_kernel<<<1, 96>>>(A, out);
}

// round 16
// speedup vs baseline: 1.5017x; 1.0520x over previous
#include <cuda_runtime.h>
#include <cstddef>

#define T_STEPS 300
#define TS_U8   304          // padded stride for u8 spike tensors (16B aligned)
#define THETA 10.0f

// ---------------- scratch ----------------
__device__ float g_bufA[39321600];          // float u scratch
__device__ unsigned char g_bufS[9961472];   // u8 spike / u8 input scratch
__device__ float g_bufW[32000];             // packed weights (w1:1280, w2:6144, w3:24576)

#define W1_OFF 0
#define W2_OFF 1280
#define W3_OFF 7424

// REF_KERNEL[1..10]: -20*t*exp(1-t), t=1..10 (fp32-rounded from double)
__constant__ float c_refk[10] = {
    -20.0f,
    -14.715177646857693f,
    -8.1201169941967624f,
    -3.9829654694291156f,
    -1.8315638888734179f,
    -0.80855363989025606f,
    -0.34702530473329019f,
    -0.14590111448872260f,
    -0.060383273022452132f,
    -0.024681960817335913f
};

__device__ __forceinline__ float spike_step(float u, float (&buf)[10]) {
    float um = u + buf[0];
    float e = (um >= THETA) ? 1.0f : 0.0f;
#pragma unroll
    for (int j = 0; j < 9; j++) buf[j] = buf[j + 1] + e * c_refk[j];
    buf[9] = e * c_refk[9];
    return e;   // TS = 1 -> amplitude 1
}

// packed 2x fp32 fma (Blackwell FFMA2). Bit-identical to two fmaf's.
__device__ __forceinline__ void ffma2(float2& c, float2 a, float2 b) {
    unsigned long long au = *reinterpret_cast<unsigned long long*>(&a);
    unsigned long long bu = *reinterpret_cast<unsigned long long*>(&b);
    unsigned long long cu = *reinterpret_cast<unsigned long long*>(&c);
    asm("fma.rn.f32x2 %0, %1, %2, %0;" : "+l"(cu) : "l"(au), "l"(bu));
    *reinterpret_cast<unsigned long long*>(&c) = cu;
}

__device__ __forceinline__ void ffma4(float4& c, const float4& a, float w) {
    float2 wv = make_float2(w, w);
    float2 clo = make_float2(c.x, c.y), chi = make_float2(c.z, c.w);
    ffma2(clo, make_float2(a.x, a.y), wv);
    ffma2(chi, make_float2(a.z, a.w), wv);
    c.x = clo.x; c.y = clo.y; c.z = chi.x; c.w = chi.y;
}

__device__ __forceinline__ float f4_get(const float4& v, int i) {
    return i == 0 ? v.x : i == 1 ? v.y : i == 2 ? v.z : v.w;
}

__device__ __forceinline__ float4 load_quad(const float* p) {
    return *(const float4*)p;
}
__device__ __forceinline__ float4 load_quad(const unsigned char* p) {
    uchar4 c = *(const uchar4*)p;
    return make_float4((float)c.x, (float)c.y, (float)c.z, (float)c.w);
}

// ---------------- weight packing: [co][ci][ky][WROW] 16B-aligned rows ---------
__global__ void pack_weights_kernel(const float* __restrict__ w1,
                                    const float* __restrict__ w2,
                                    const float* __restrict__ w3,
                                    float* __restrict__ wp)
{
    int i = blockIdx.x * blockDim.x + threadIdx.x;
    if (i < 1280) {                       // w1: [16][2][5][8]
        int kx = i % 8; int r = i / 8;
        int ky = r % 5; r /= 5;
        int ci = r % 2; int co = r / 2;
        wp[W1_OFF + i] = (kx < 5) ? w1[((co * 2 + ci) * 5 + ky) * 5 + kx] : 0.0f;
    } else if (i < 1280 + 6144) {         // w2: [32][16][3][4]
        int k = i - 1280;
        int kx = k % 4; int r = k / 4;
        int ky = r % 3; r /= 3;
        int ci = r % 16; int co = r / 16;
        wp[W2_OFF + k] = (kx < 3) ? w2[((co * 16 + ci) * 3 + ky) * 3 + kx] : 0.0f;
    } else if (i < 1280 + 6144 + 24576) { // w3: [64][32][3][4]
        int k = i - 1280 - 6144;
        int kx = k % 4; int r = k / 4;
        int ky = r % 3; r /= 3;
        int ci = r % 32; int co = r / 32;
        wp[W3_OFF + k] = (kx < 3) ? w3[((co * 32 + ci) * 3 + ky) * 3 + kx] : 0.0f;
    }
}

// ---------------- input fp32 {0,1} -> u8 (exact) ----------------
__global__ void x_to_u8_kernel(const float* __restrict__ x, unsigned char* __restrict__ y)
{
    int i = blockIdx.x * blockDim.x + threadIdx.x;
    if (i < 1387200) {
        float4 v = ((const float4*)x)[i];
        ((uchar4*)y)[i] = make_uchar4((unsigned char)v.x, (unsigned char)v.y,
                                      (unsigned char)v.z, (unsigned char)v.w);
    }
}

// ---------------- conv: float4 over time, XR=4, COB=4, YB output rows ---------
// block: (b, yo-group of YB rows, t-chunk of 4*TPQ steps). threads (TPQ, 32).
// Tile holds K+YB-1 padded input rows; each ty computes its (co,x) item for
// all YB rows sequentially -> tile loads amortized over YB outputs.
template <typename IT, int IN_TS,
          int Ci, int Hi, int Wi, int Co, int Ho, int Wo, int K, int PAD, int TPQ,
          int WROW, int YB>
__global__ void __launch_bounds__(TPQ * 32, 2)
conv_kernel(const IT* __restrict__ in, const float* __restrict__ w,
            float* __restrict__ out)
{
    constexpr int WT  = Wo + K - 1;
    constexpr int RT  = K + YB - 1;       // tile rows
    constexpr int XR  = 4;
    constexpr int COB = 4;
    constexpr int XG  = Wo / XR;
    constexpr int CG  = Co / COB;
    static_assert(XG * CG == 32, "one item per ty");
    constexpr int TCH = 4 * TPQ;
    constexpr int NTC = (T_STEPS + TCH - 1) / TCH;
    constexpr int NTH = TPQ * 32;

    extern __shared__ char smraw[];
    float4* sm4 = (float4*)smraw;

    int bid = blockIdx.x;
    int tc  = bid % NTC;
    int yg  = (bid / NTC) % (Ho / YB);
    int b   = bid / (NTC * (Ho / YB));
    int yo0 = yg * YB;
    int t0  = tc * TCH;

    int tid = threadIdx.y * TPQ + threadIdx.x;

    // ---- load padded input tile: [Ci][RT][WT][TPQ] float4 ----
    constexpr int TILE4 = Ci * RT * WT * TPQ;
    for (int flat = tid; flat < TILE4; flat += NTH) {
        int tt = flat % TPQ;
        int r  = flat / TPQ;
        int xw = r % WT; r /= WT;
        int rr = r % RT;
        int ci = r / RT;
        int xi = xw - PAD;
        int yi = yo0 - PAD + rr;
        int t  = t0 + 4 * tt;
        float4 v = make_float4(0.0f, 0.0f, 0.0f, 0.0f);
        if (xi >= 0 && xi < Wi && yi >= 0 && yi < Hi && t < T_STEPS)
            v = load_quad(&in[((((size_t)b * Ci + ci) * Hi + yi) * Wi + xi) * IN_TS + t]);
        sm4[flat] = v;
    }
    __syncthreads();

    int tx = threadIdx.x;
    int t  = t0 + 4 * tx;
    int item = threadIdx.y;
    int co0 = (item / XG) * COB;
    int xo0 = (item % XG) * XR;

#pragma unroll
    for (int yb = 0; yb < YB; yb++) {
        int yo = yo0 + yb;

        float4 acc[COB][XR];
#pragma unroll
        for (int j = 0; j < COB; j++)
#pragma unroll
            for (int r = 0; r < XR; r++) acc[j][r] = make_float4(0.0f, 0.0f, 0.0f, 0.0f);

        for (int ci = 0; ci < Ci; ci++) {
#pragma unroll
            for (int ky = 0; ky < K; ky++) {
                float4 v[K + XR - 1];
                const float4* sp = &sm4[((ci * RT + yb + ky) * WT + xo0) * TPQ + tx];
#pragma unroll
                for (int j = 0; j < K + XR - 1; j++) v[j] = sp[j * TPQ];
                float4 wq[COB][WROW / 4];
#pragma unroll
                for (int j = 0; j < COB; j++)
#pragma unroll
                    for (int p = 0; p < WROW / 4; p++)
                        wq[j][p] = *(const float4*)&w[(((size_t)(co0 + j) * Ci + ci) * K + ky) * WROW + 4 * p];
#pragma unroll
                for (int kx = 0; kx < K; kx++)
#pragma unroll
                    for (int j = 0; j < COB; j++)
#pragma unroll
                        for (int r = 0; r < XR; r++)
                            ffma4(acc[j][r], v[kx + r], f4_get(wq[j][kx >> 2], kx & 3));
            }
        }

        if (t < T_STEPS) {
#pragma unroll
            for (int j = 0; j < COB; j++)
#pragma unroll
                for (int r = 0; r < XR; r++)
                    *(float4*)&out[((((size_t)b * Co + co0 + j) * Ho + yo) * Wo + xo0 + r) * T_STEPS + t]
                        = acc[j][r];
        }
    }
}

// ---------------- fused spike -> 2x2 sum-pool (x11) -> spike, u8 out ----------
// WARP-COOPERATIVE: 4 lanes per pooled neuron; 16-step pipelined; 128-thr blocks.
__device__ __forceinline__ unsigned int pool_quad(float4 uv, float (&bufp)[10],
                                                  float (&bp)[10]) {
    float p0 = spike_step(uv.x, bufp);
    float p1 = spike_step(uv.y, bufp);
    float p2 = spike_step(uv.z, bufp);
    float p3 = spike_step(uv.w, bufp);
    p0 += __shfl_xor_sync(0xffffffffu, p0, 1); p0 += __shfl_xor_sync(0xffffffffu, p0, 2);
    p1 += __shfl_xor_sync(0xffffffffu, p1, 1); p1 += __shfl_xor_sync(0xffffffffu, p1, 2);
    p2 += __shfl_xor_sync(0xffffffffu, p2, 1); p2 += __shfl_xor_sync(0xffffffffu, p2, 2);
    p3 += __shfl_xor_sync(0xffffffffu, p3, 1); p3 += __shfl_xor_sync(0xffffffffu, p3, 2);
    unsigned int e0 = (unsigned int)spike_step(11.0f * p0, bp);
    unsigned int e1 = (unsigned int)spike_step(11.0f * p1, bp);
    unsigned int e2 = (unsigned int)spike_step(11.0f * p2, bp);
    unsigned int e3 = (unsigned int)spike_step(11.0f * p3, bp);
    return e0 | (e1 << 8) | (e2 << 16) | (e3 << 24);
}

__global__ void __launch_bounds__(128)
spikepool_kernel(const float* __restrict__ u, unsigned char* __restrict__ s,
                 int C, int Ho, int Wo)
{
    int idx = blockIdx.x * 128 + threadIdx.x;
    int sub = idx & 3;
    int n   = idx >> 2;
    int total = 8 * C * Ho * Wo;
    if (n >= total) return;
    int x  = n % Wo;
    int y  = (n / Wo) % Ho;
    int cb = n / (Wo * Ho);

    int dy = sub >> 1, dx = sub & 1;
    size_t base = (((size_t)cb * (2 * Ho) + 2 * y + dy) * (2 * Wo) + 2 * x + dx) * T_STEPS;
    const float4* up = (const float4*)(u + base);
    unsigned char* sp = s + (size_t)n * TS_U8;

    float bufp[10], bp[10];
#pragma unroll
    for (int j = 0; j < 10; j++) { bufp[j] = 0.0f; bp[j] = 0.0f; }

    for (int g = 0; g < 18; g++) {
        float4 v[4];
#pragma unroll
        for (int i = 0; i < 4; i++) v[i] = up[g * 4 + i];
        unsigned int wd[4];
#pragma unroll
        for (int i = 0; i < 4; i++) wd[i] = pool_quad(v[i], bufp, bp);
        if (sub == 0)
            ((uint4*)sp)[g] = make_uint4(wd[0], wd[1], wd[2], wd[3]);
    }
    {
        float4 v[3];
#pragma unroll
        for (int i = 0; i < 3; i++) v[i] = up[72 + i];
#pragma unroll
        for (int i = 0; i < 3; i++) {
            unsigned int wd = pool_quad(v[i], bufp, bp);
            if (sub == 0) ((unsigned int*)sp)[72 + i] = wd;
        }
    }
}

// ---------------- spike with u8 output (layer 5), 64-thr blocks ----------------
__global__ void __launch_bounds__(64)
spike_u8_kernel(const float* __restrict__ u, unsigned char* __restrict__ s, int nNeurons)
{
    int n = blockIdx.x * 64 + threadIdx.x;
    if (n >= nNeurons) return;
    const float4* up = (const float4*)(u + (size_t)n * T_STEPS);
    unsigned char* sp = s + (size_t)n * TS_U8;
    float buf[10];
#pragma unroll
    for (int j = 0; j < 10; j++) buf[j] = 0.0f;

    for (int g = 0; g < 18; g++) {
        float4 v[4];
#pragma unroll
        for (int i = 0; i < 4; i++) v[i] = up[g * 4 + i];
        unsigned int wd[4];
#pragma unroll
        for (int i = 0; i < 4; i++) {
            unsigned int e0 = (unsigned int)spike_step(v[i].x, buf);
            unsigned int e1 = (unsigned int)spike_step(v[i].y, buf);
            unsigned int e2 = (unsigned int)spike_step(v[i].z, buf);
            unsigned int e3 = (unsigned int)spike_step(v[i].w, buf);
            wd[i] = e0 | (e1 << 8) | (e2 << 16) | (e3 << 24);
        }
        ((uint4*)sp)[g] = make_uint4(wd[0], wd[1], wd[2], wd[3]);
    }
    {
        float4 v[3];
#pragma unroll
        for (int i = 0; i < 3; i++) v[i] = up[72 + i];
#pragma unroll
        for (int i = 0; i < 3; i++) {
            unsigned int e0 = (unsigned int)spike_step(v[i].x, buf);
            unsigned int e1 = (unsigned int)spike_step(v[i].y, buf);
            unsigned int e2 = (unsigned int)spike_step(v[i].z, buf);
            unsigned int e3 = (unsigned int)spike_step(v[i].w, buf);
            ((unsigned int*)sp)[72 + i] = e0 | (e1 << 8) | (e2 << 16) | (e3 << 24);
        }
    }
}

// ---------------- FC: block = (b, t-quad); s5 chunk staged in smem ------------
__global__ void __launch_bounds__(320, 3)
fc_kernel(const unsigned char* __restrict__ s5, const float* __restrict__ wfc,
          float* __restrict__ u_out)
{
    constexpr int NQ = T_STEPS / 4;
    int q = blockIdx.x % NQ;
    int b = blockIdx.x / NQ;
    int t0 = q * 4;

    extern __shared__ float4 s_sm[];
    int tid = threadIdx.y * 32 + threadIdx.x;

    const unsigned char* sb = s5 + (size_t)b * 4096 * TS_U8 + t0;
    for (int c = tid; c < 4096; c += 320) {
        uchar4 cc = *(const uchar4*)&sb[(size_t)c * TS_U8];
        s_sm[c] = make_float4((float)cc.x, (float)cc.y, (float)cc.z, (float)cc.w);
    }
    __syncthreads();

    int o    = threadIdx.y;
    int lane = threadIdx.x;
    const float* wo = wfc + o * 4096;

    float4 acc = make_float4(0.0f, 0.0f, 0.0f, 0.0f);
    for (int c = lane; c < 4096; c += 32) {
        float4 v = s_sm[c];
        float wgt = __ldg(&wo[c]);
        acc.x = fmaf(v.x, wgt, acc.x);
        acc.y = fmaf(v.y, wgt, acc.y);
        acc.z = fmaf(v.z, wgt, acc.z);
        acc.w = fmaf(v.w, wgt, acc.w);
    }
#pragma unroll
    for (int d = 16; d >= 1; d >>= 1) {
        acc.x += __shfl_xor_sync(0xffffffffu, acc.x, d);
        acc.y += __shfl_xor_sync(0xffffffffu, acc.y, d);
        acc.z += __shfl_xor_sync(0xffffffffu, acc.z, d);
        acc.w += __shfl_xor_sync(0xffffffffu, acc.w, d);
    }
    if (lane == 0)
        *(float4*)&u_out[(size_t)(b * 10 + o) * T_STEPS + t0] = acc;
}

// ---------------- final spike on 80 neurons ----------------
__global__ void spike_final_kernel(const float* __restrict__ u, float* __restrict__ out)
{
    int n = threadIdx.x;
    if (n >= 80) return;
    const float4* up = (const float4*)(u + (size_t)n * T_STEPS);
    float4*       sp = (float4*)(out + (size_t)n * T_STEPS);
    float buf[10];
#pragma unroll
    for (int j = 0; j < 10; j++) buf[j] = 0.0f;
    for (int q = 0; q < T_STEPS / 4; q++) {
        float4 uv = up[q];
        float4 ev;
        ev.x = spike_step(uv.x, buf);
        ev.y = spike_step(uv.y, buf);
        ev.z = spike_step(uv.z, buf);
        ev.w = spike_step(uv.w, buf);
        sp[q] = ev;
    }
}

// ---------------- launcher ----------------
extern "C" void kernel_launch(void* const* d_in, const int* in_sizes, int n_in,
                              void* d_out, int out_size)
{
    const float* x   = (const float*)d_in[0];
    const float* w1  = (const float*)d_in[1];
    const float* w2  = (const float*)d_in[2];
    const float* w3  = (const float*)d_in[3];
    const float* wfc = (const float*)d_in[4];
    float* out = (float*)d_out;

    float *A = nullptr, *W = nullptr;
    unsigned char *S = nullptr;
    cudaGetSymbolAddress((void**)&A, g_bufA);
    cudaGetSymbolAddress((void**)&S, g_bufS);
    cudaGetSymbolAddress((void**)&W, g_bufW);

    constexpr int SM1 = 2  * 5 * 6 * 36 * 8 * 16 / 5;  // Ci*RT*WT*TPQ*16 = 2*6*36*8*16 = 55296
    constexpr int SM2 = 16 * 3 * 18 * 8 * 16;          // 110592  (TPQ=8, YB=1)
    constexpr int SM3 = 32 * 3 * 10 * 6 * 16;          //  92160  (TPQ=6, YB=1)
    constexpr int SMF = 4096 * 16;                     //  65536

    cudaFuncSetAttribute((const void*)conv_kernel<unsigned char,T_STEPS,2,34,34,16,32,32,5,1,8,8,2>,
                         cudaFuncAttributeMaxDynamicSharedMemorySize, SM1);
    cudaFuncSetAttribute((const void*)conv_kernel<unsigned char,TS_U8,16,16,16,32,16,16,3,1,8,4,1>,
                         cudaFuncAttributeMaxDynamicSharedMemorySize, SM2);
    cudaFuncSetAttribute((const void*)conv_kernel<unsigned char,TS_U8,32,8,8,64,8,8,3,1,6,4,1>,
                         cudaFuncAttributeMaxDynamicSharedMemorySize, SM3);
    cudaFuncSetAttribute((const void*)fc_kernel,
                         cudaFuncAttributeMaxDynamicSharedMemorySize, SMF);

    constexpr int NTC8 = 10;   // ceil(300/32)
    constexpr int NTC6 = 13;   // ceil(300/24)

    // prep: pack weights, convert input to u8
    pack_weights_kernel<<<(32000 + 255) / 256, 256>>>(w1, w2, w3, W);
    x_to_u8_kernel<<<(1387200 + 255) / 256, 256>>>(x, S);

    // L1: conv 2->16 5x5 pad1, YB=2 row pairs : S(x_u8) -> A (u1)
    conv_kernel<unsigned char,T_STEPS,2,34,34,16,32,32,5,1,8,8,2>
        <<<8 * 16 * NTC8, dim3(8, 32), SM1>>>(S, W + W1_OFF, A);
    // spike1 + pool + spike2 fused (4 lanes/neuron): A -> S (s2, u8)
    spikepool_kernel<<<(32768 * 4) / 128, 128>>>(A, S, 16, 16, 16);
    // L2: conv 16->32 3x3 pad1 : S -> A (u3)
    conv_kernel<unsigned char,TS_U8,16,16,16,32,16,16,3,1,8,4,1>
        <<<8 * 16 * NTC8, dim3(8, 32), SM2>>>(S, W + W2_OFF, A);
    // spike3 + pool + spike4 fused (4 lanes/neuron): A -> S (s4, u8)
    spikepool_kernel<<<(16384 * 4) / 128, 128>>>(A, S, 32, 8, 8);
    // L3: conv 32->64 3x3 pad1 : S -> A (u5)
    conv_kernel<unsigned char,TS_U8,32,8,8,64,8,8,3,1,6,4,1>
        <<<8 * 8 * NTC6, dim3(6, 32), SM3>>>(S, W + W3_OFF, A);
    // spike5: A -> S (s5, u8)
    spike_u8_kernel<<<32768 / 64, 64>>>(A, S, 32768);
    // FC: S (s5) -> A (u6)
    fc_kernel<<<8 * 75, dim3(32, 10), SMF>>>(S, wfc, A);
    // final spike: A -> out
    spike_final_kernel<<<1, 96>>>(A, out);
}